// round 6
// baseline (speedup 1.0000x reference)
#include <cuda_runtime.h>
#include <cuda_bf16.h>

#define NN 10000
#define NE 80000

// ---------------- scratch (static device memory, no allocs) ----------------
__device__ int   g_deg[NN];
__device__ int   g_offs[NN + 1];
__device__ int   g_cursor[NN];
__device__ int   g_csr[NE];
__device__ float g_h1e[NE * 25];      // relu(ea@nn1_w1+b1)
__device__ float g_h2e[NE * 25];      // relu(ea@nn2_w1+b2_1)
__device__ float g_A1[NN * 432];      // [S1/deg | Xsum1/deg | x]
__device__ float g_A2[NN * 864];      // [S2/deg | Hsum/deg | h1]
__device__ float g_W1[432 * 32];      // [w2_re ; b2_re ; root]
__device__ float g_W2[864 * 64];
__device__ float g_t1[NN * 32];       // elu(conv1) pre-BN
__device__ float g_t2[NN * 64];       // elu(conv2) pre-BN
__device__ float g_bn[256];           // sum1[0:32] sq1[64:96] sum2[128:192] sq2[192:256]

__device__ __forceinline__ float eluf(float x) { return x > 0.f ? x : expm1f(x); }

// ---- packed f32x2 helpers (Blackwell FFMA2: 2x fp32 throughput) ----
typedef unsigned long long ull;
__device__ __forceinline__ ull pack2(float lo, float hi) {
    ull d; asm("mov.b64 %0, {%1, %2};" : "=l"(d) : "f"(lo), "f"(hi)); return d;
}
__device__ __forceinline__ void unpack2(ull v, float& lo, float& hi) {
    asm("mov.b64 {%0, %1}, %2;" : "=f"(lo), "=f"(hi) : "l"(v));
}
__device__ __forceinline__ ull ffma2(ull a, ull b, ull c) {
    ull d; asm("fma.rn.f32x2 %0, %1, %2, %3;" : "=l"(d) : "l"(a), "l"(b), "l"(c)); return d;
}

// ---------------- init ----------------
__global__ void k_init(float* out) {
    int i = blockIdx.x * blockDim.x + threadIdx.x;
    if (i < NN) g_deg[i] = 0;
    if (i < 256) g_bn[i] = 0.f;
    if (i == 0) out[0] = 0.f;
}

// ---------------- fused: edge MLP + degree atomics + weight-augment prep ----------------
template <int CIN, int COUT>
__device__ __forceinline__ void prepW_elem(int idx, const float* __restrict__ w2,
                                           const float* __restrict__ b2,
                                           const float* __restrict__ root,
                                           float* __restrict__ W) {
    constexpr int KA = 25 * CIN + 2 * CIN;
    if (idx >= KA * COUT) return;
    int kidx = idx / COUT, o = idx % COUT;
    float v;
    if (kidx < 25 * CIN) {
        int k = kidx / CIN, i = kidx % CIN;
        v = w2[(k * CIN + i) * COUT + o];
    } else if (kidx < 25 * CIN + CIN) {
        int i = kidx - 25 * CIN;
        v = b2[i * COUT + o];
    } else {
        int i = kidx - 25 * CIN - CIN;
        v = root[i * COUT + o];
    }
    W[idx] = v;
}

__global__ void __launch_bounds__(256) k_edge(
        const float* __restrict__ ea, const int* __restrict__ ei,
        const float* __restrict__ w1a, const float* __restrict__ b1a,
        const float* __restrict__ w1b, const float* __restrict__ b1b,
        const float* __restrict__ w2a, const float* __restrict__ b2a, const float* __restrict__ roota,
        const float* __restrict__ w2b, const float* __restrict__ b2b, const float* __restrict__ rootb) {
    __shared__ float sA[225];
    __shared__ float sB[225];
    int bid = blockIdx.x, tid = threadIdx.x;
    if (bid < 313) {
        for (int l = tid; l < 225; l += 256) {
            sA[l] = (l < 200) ? w1a[l] : b1a[l - 200];
            sB[l] = (l < 200) ? w1b[l] : b1b[l - 200];
        }
        __syncthreads();
        int e = bid * 256 + tid;
        if (e >= NE) return;
        atomicAdd(&g_deg[ei[NE + e]], 1);
        float4 a0 = *(const float4*)&ea[e * 8];
        float4 a1 = *(const float4*)&ea[e * 8 + 4];
        float a[8] = {a0.x, a0.y, a0.z, a0.w, a1.x, a1.y, a1.z, a1.w};
        #pragma unroll
        for (int k = 0; k < 25; k++) {
            float s = sA[200 + k];
            #pragma unroll
            for (int i = 0; i < 8; i++) s += a[i] * sA[i * 25 + k];
            g_h1e[e * 25 + k] = fmaxf(s, 0.f);
        }
        #pragma unroll
        for (int k = 0; k < 25; k++) {
            float s = sB[200 + k];
            #pragma unroll
            for (int i = 0; i < 8; i++) s += a[i] * sB[i * 25 + k];
            g_h2e[e * 25 + k] = fmaxf(s, 0.f);
        }
    } else if (bid < 313 + 54) {
        prepW_elem<16, 32>((bid - 313) * 256 + tid, w2a, b2a, roota, g_W1);
    } else {
        prepW_elem<32, 64>((bid - 367) * 256 + tid, w2b, b2b, rootb, g_W2);
    }
}

// ---------------- exclusive scan over 10000 degrees (single block) ----------------
__global__ void k_scan() {
    __shared__ int part[1024];
    int t = threadIdx.x;
    int base = t * 10;
    int s = 0;
    if (base < NN) {
        #pragma unroll
        for (int j = 0; j < 10; j++) if (base + j < NN) s += g_deg[base + j];
    }
    part[t] = s;
    __syncthreads();
    for (int off = 1; off < 1024; off <<= 1) {
        int v = 0;
        if (t >= off) v = part[t - off];
        __syncthreads();
        part[t] += v;
        __syncthreads();
    }
    int excl = (t == 0) ? 0 : part[t - 1];
    if (base < NN) {
        int run = excl;
        #pragma unroll
        for (int j = 0; j < 10; j++) {
            if (base + j < NN) {
                g_offs[base + j] = run;
                g_cursor[base + j] = run;
                run += g_deg[base + j];
            }
        }
    }
    if (t == 1023) g_offs[NN] = part[1023];
}

// ---------------- CSR fill ----------------
__global__ void k_fill(const int* __restrict__ ei) {
    int e = blockIdx.x * blockDim.x + threadIdx.x;
    if (e < NE) {
        int d = ei[NE + e];
        int pos = atomicAdd(&g_cursor[d], 1);
        g_csr[pos] = e;
    }
}

// ------- per-node gather of rank-1 outer products; optional fused BN+ELU on features ----
template <int CIN, bool BN>
__global__ void __launch_bounds__(256) k_gather(const int* __restrict__ ei,
                                                const float* __restrict__ xfeat,
                                                const float* __restrict__ hE,
                                                float* __restrict__ A,
                                                const float* __restrict__ gamma,
                                                const float* __restrict__ beta,
                                                const float* __restrict__ bsum,
                                                const float* __restrict__ bsq) {
    constexpr int SW = 25 * CIN;
    constexpr int KA = SW + 2 * CIN;
    constexpr int NACC = (SW + 255) / 256;
    constexpr int EB = 8;
    constexpr int EW = 25 + CIN;
    constexpr int LOADS = EB * EW;
    int n = blockIdx.x;
    int t = threadIdx.x;
    __shared__ float shh[EB][25];
    __shared__ float shx[EB][CIN];
    __shared__ float s_scale[CIN];
    __shared__ float s_shift[CIN];
    if (BN) {
        if (t < CIN) {
            float m = bsum[t] * (1.f / NN);
            float var = bsq[t] * (1.f / NN) - m * m;
            float inv = rsqrtf(var + 1e-5f);
            float sc = inv * gamma[t];
            s_scale[t] = sc;
            s_shift[t] = beta[t] - m * sc;
        }
        __syncthreads();
    }
    float acc[NACC];
    #pragma unroll
    for (int j = 0; j < NACC; j++) acc[j] = 0.f;
    float xs = 0.f;
    int e0 = g_offs[n], e1 = g_offs[n + 1];

    for (int p0 = e0; p0 < e1; p0 += EB) {
        int cnt = e1 - p0; if (cnt > EB) cnt = EB;
        #pragma unroll
        for (int l = t; l < LOADS; l += 256) {
            int j = l / EW, r = l - j * EW;
            float v = 0.f;
            if (j < cnt) {
                int e = __ldg(&g_csr[p0 + j]);
                if (r < 25) v = hE[e * 25 + r];
                else {
                    int c = r - 25;
                    v = xfeat[__ldg(&ei[e]) * CIN + c];
                    if (BN) v = eluf(v * s_scale[c] + s_shift[c]);
                }
            }
            if (r < 25) shh[j][r] = v;
            else        shx[j][r - 25] = v;
        }
        __syncthreads();
        #pragma unroll
        for (int j = 0; j < EB; j++) {
            #pragma unroll
            for (int na = 0; na < NACC; na++) {
                int idx = t + na * 256;
                if (idx < SW) acc[na] += shh[j][idx / CIN] * shx[j][idx % CIN];
            }
        }
        if (t < CIN) {
            #pragma unroll
            for (int j = 0; j < EB; j++) xs += shx[j][t];
        }
        __syncthreads();
    }
    float inv = 1.f / fmaxf((float)(e1 - e0), 1.f);
    #pragma unroll
    for (int na = 0; na < NACC; na++) {
        int idx = t + na * 256;
        if (idx < SW) A[n * KA + idx] = acc[na] * inv;
    }
    if (t < CIN) {
        A[n * KA + SW + t] = xs * inv;
        float sv = xfeat[n * CIN + t];
        if (BN) sv = eluf(sv * s_scale[t] + s_shift[t]);
        A[n * KA + SW + CIN + t] = sv;
    }
}

// ------- dense GEMM  out = elu(A @ W + bias), f32x2 FMA, fused BN-stats epilogue -------
// BM=40, 320 threads: each thread = 1 row x TC cols. grid=250 -> max 2 tiles/SM.
template <int KA, int COUT, int BK>
__global__ void __launch_bounds__(320) k_gemm(const float* __restrict__ A,
                                              const float* __restrict__ W,
                                              const float* __restrict__ bias,
                                              float* __restrict__ out,
                                              float* __restrict__ bnsum,
                                              float* __restrict__ bnsq) {
    constexpr int BM = 40;
    constexpr int TC = COUT / 8;   // 4 or 8 cols per thread
    constexpr int NP = TC / 2;     // 2 or 4 f32x2 pairs
    __shared__ float As[BK][BM];
    __shared__ float Bs[BK * COUT];
    __shared__ float Ssum[BM][COUT];
    __shared__ float Ssq[BM][COUT];
    int tid = threadIdx.x;
    int tx = tid & 7, ty = tid >> 3;    // tx: col group 0..7, ty: row 0..39
    int row0 = blockIdx.x * BM;

    ull acc[NP];
    #pragma unroll
    for (int p = 0; p < NP; p++) acc[p] = 0ull;

    for (int k0 = 0; k0 < KA; k0 += BK) {
        constexpr int AF4 = BM * BK / 4;
        #pragma unroll
        for (int l = tid; l < AF4; l += 320) {
            int r = l / (BK / 4), q = l % (BK / 4);
            int gr = row0 + r;
            float4 v = make_float4(0.f, 0.f, 0.f, 0.f);
            if (gr < NN) v = *(const float4*)&A[gr * KA + k0 + q * 4];
            As[q * 4 + 0][r] = v.x;
            As[q * 4 + 1][r] = v.y;
            As[q * 4 + 2][r] = v.z;
            As[q * 4 + 3][r] = v.w;
        }
        constexpr int BF4 = BK * COUT / 4;
        const float4* Wp = (const float4*)&W[k0 * COUT];
        #pragma unroll
        for (int l = tid; l < BF4; l += 320) ((float4*)Bs)[l] = Wp[l];
        __syncthreads();

        #pragma unroll
        for (int kk = 0; kk < BK; kk++) {
            float a = As[kk][ty];
            ull aa = pack2(a, a);
            #pragma unroll
            for (int q = 0; q < NP / 2; q++) {
                float4 b4 = *(const float4*)&Bs[kk * COUT + tx * TC + q * 4];
                acc[2 * q]     = ffma2(aa, pack2(b4.x, b4.y), acc[2 * q]);
                acc[2 * q + 1] = ffma2(aa, pack2(b4.z, b4.w), acc[2 * q + 1]);
            }
        }
        __syncthreads();
    }

    int n = row0 + ty;
    bool valid = (n < NN);
    #pragma unroll
    for (int p = 0; p < NP; p++) {
        float lo, hi;
        unpack2(acc[p], lo, hi);
        int o = tx * TC + p * 2;
        float v0 = eluf(lo + bias[o]);
        float v1 = eluf(hi + bias[o + 1]);
        if (valid) *(float2*)&out[n * COUT + o] = make_float2(v0, v1);
        if (!valid) { v0 = 0.f; v1 = 0.f; }
        Ssum[ty][o] = v0;      Ssum[ty][o + 1] = v1;
        Ssq[ty][o]  = v0 * v0; Ssq[ty][o + 1]  = v1 * v1;
    }
    __syncthreads();
    for (int o = tid; o < COUT; o += 320) {
        float s = 0.f, q = 0.f;
        #pragma unroll 8
        for (int r = 0; r < BM; r++) { s += Ssum[r][o]; q += Ssq[r][o]; }
        atomicAdd(&bnsum[o], s);
        atomicAdd(&bnsq[o], q);
    }
}

// ---------------- FC head + global sum, fused BN2 finalize+apply ----------------
__global__ void __launch_bounds__(256) k_fc(const float* __restrict__ t2,
                                            const float* __restrict__ w1,
                                            const float* __restrict__ b1,
                                            const float* __restrict__ w2,
                                            const float* __restrict__ b2,
                                            const float* __restrict__ gamma,
                                            const float* __restrict__ beta,
                                            const float* __restrict__ bsum,
                                            const float* __restrict__ bsq,
                                            float* __restrict__ out) {
    __shared__ float sw[64 * 128];
    int tid = threadIdx.x;
    int lane = tid & 31, warp = tid >> 5;
    #pragma unroll
    for (int l = tid; l < 64 * 128 / 4; l += 256)
        ((float4*)sw)[l] = ((const float4*)w1)[l];
    float b1v[4], w2v[4];
    #pragma unroll
    for (int j = 0; j < 4; j++) {
        b1v[j] = b1[j * 32 + lane];
        w2v[j] = w2[j * 32 + lane];
    }
    float b2v = b2[0];
    // per-lane BN constants for channels `lane` and `lane+32`
    float scl0, sft0, scl1, sft1;
    {
        float m = bsum[lane] * (1.f / NN);
        float var = bsq[lane] * (1.f / NN) - m * m;
        scl0 = rsqrtf(var + 1e-5f) * gamma[lane];
        sft0 = beta[lane] - m * scl0;
        int c = lane + 32;
        m = bsum[c] * (1.f / NN);
        var = bsq[c] * (1.f / NN) - m * m;
        scl1 = rsqrtf(var + 1e-5f) * gamma[c];
        sft1 = beta[c] - m * scl1;
    }
    __syncthreads();

    float local = 0.f;
    for (int n = blockIdx.x * 8 + warp; n < NN; n += gridDim.x * 8) {
        float hv0 = eluf(t2[n * 64 + lane] * scl0 + sft0);
        float hv1 = eluf(t2[n * 64 + 32 + lane] * scl1 + sft1);
        float s0 = b1v[0], s1 = b1v[1], s2 = b1v[2], s3 = b1v[3];
        #pragma unroll
        for (int i = 0; i < 64; i++) {
            float hv = __shfl_sync(0xffffffffu, (i < 32) ? hv0 : hv1, i & 31);
            s0 += hv * sw[i * 128 + lane];
            s1 += hv * sw[i * 128 + 32 + lane];
            s2 += hv * sw[i * 128 + 64 + lane];
            s3 += hv * sw[i * 128 + 96 + lane];
        }
        float contrib = eluf(s0) * w2v[0] + eluf(s1) * w2v[1]
                      + eluf(s2) * w2v[2] + eluf(s3) * w2v[3];
        #pragma unroll
        for (int off = 16; off > 0; off >>= 1)
            contrib += __shfl_xor_sync(0xffffffffu, contrib, off);
        if (lane == 0) local += eluf(contrib + b2v);
    }
    if (lane == 0) atomicAdd(out, local);
}

// ---------------- launch ----------------
extern "C" void kernel_launch(void* const* d_in, const int* in_sizes, int n_in,
                              void* d_out, int out_size) {
    const float* x        = (const float*)d_in[0];
    const int*   ei       = (const int*)d_in[1];
    const float* ea       = (const float*)d_in[2];
    const float* nn1_w1   = (const float*)d_in[3];
    const float* nn1_b1   = (const float*)d_in[4];
    const float* nn1_w2   = (const float*)d_in[5];
    const float* nn1_b2   = (const float*)d_in[6];
    const float* c1_root  = (const float*)d_in[7];
    const float* c1_bias  = (const float*)d_in[8];
    const float* bn1_g    = (const float*)d_in[9];
    const float* bn1_b    = (const float*)d_in[10];
    const float* nn2_w1   = (const float*)d_in[11];
    const float* nn2_b1   = (const float*)d_in[12];
    const float* nn2_w2   = (const float*)d_in[13];
    const float* nn2_b2   = (const float*)d_in[14];
    const float* c2_root  = (const float*)d_in[15];
    const float* c2_bias  = (const float*)d_in[16];
    const float* bn2_g    = (const float*)d_in[17];
    const float* bn2_b    = (const float*)d_in[18];
    const float* fc1_w    = (const float*)d_in[19];
    const float* fc1_b    = (const float*)d_in[20];
    const float* fc2_w    = (const float*)d_in[21];
    const float* fc2_b    = (const float*)d_in[22];
    float* out = (float*)d_out;

    float *pA1, *pA2, *pW1, *pW2, *ph1e, *ph2e, *pt1, *pt2, *pbn;
    cudaGetSymbolAddress((void**)&pA1, g_A1);
    cudaGetSymbolAddress((void**)&pA2, g_A2);
    cudaGetSymbolAddress((void**)&pW1, g_W1);
    cudaGetSymbolAddress((void**)&pW2, g_W2);
    cudaGetSymbolAddress((void**)&ph1e, g_h1e);
    cudaGetSymbolAddress((void**)&ph2e, g_h2e);
    cudaGetSymbolAddress((void**)&pt1, g_t1);
    cudaGetSymbolAddress((void**)&pt2, g_t2);
    cudaGetSymbolAddress((void**)&pbn, g_bn);

    k_init<<<40, 256>>>(out);
    k_edge<<<583, 256>>>(ea, ei, nn1_w1, nn1_b1, nn2_w1, nn2_b1,
                         nn1_w2, nn1_b2, c1_root, nn2_w2, nn2_b2, c2_root);
    k_scan<<<1, 1024>>>();
    k_fill<<<313, 256>>>(ei);

    // conv1: gather (no BN) -> gemm (+bn1 stats)
    k_gather<16, false><<<NN, 256>>>(ei, x, ph1e, pA1, nullptr, nullptr, nullptr, nullptr);
    k_gemm<432, 32, 16><<<250, 320>>>(pA1, pW1, c1_bias, pt1, pbn + 0, pbn + 64);

    // conv2: gather (fused bn1 finalize+apply) -> gemm (+bn2 stats)
    k_gather<32, true><<<NN, 256>>>(ei, pt1, ph2e, pA2, bn1_g, bn1_b, pbn + 0, pbn + 64);
    k_gemm<864, 64, 32><<<250, 320>>>(pA2, pW2, c2_bias, pt2, pbn + 128, pbn + 192);

    // head: fused bn2 finalize+apply + fc1 + fc2 + global sum
    k_fc<<<148, 256>>>(pt2, fc1_w, fc1_b, fc2_w, fc2_b,
                       bn2_g, bn2_b, pbn + 128, pbn + 192, out);
}

// round 7
// speedup vs baseline: 1.1468x; 1.1468x over previous
#include <cuda_runtime.h>
#include <cuda_bf16.h>

#define NN 10000
#define NE 80000
#define NBLK 148          // persistent front kernel: 1 block/SM, residency guaranteed
#define NTHR 256
#define CHUNK 68          // ceil(NN/148)

// ---------------- scratch (static device memory, no allocs) ----------------
__device__ int   g_deg[NN];
__device__ int   g_offs[NN + 1];
__device__ int   g_cursor[NN];
__device__ int   g_csr[NE];
__device__ int   g_part[NBLK];
__device__ int   g_ppre[NBLK];
__device__ float g_h1e[NE * 25];      // relu(ea@nn1_w1+b1)
__device__ float g_h2e[NE * 25];      // relu(ea@nn2_w1+b2_1)
__device__ float g_A1[NN * 432];      // [S1/deg | Xsum1/deg | x]
__device__ float g_A2[NN * 864];      // [S2/deg | Hsum/deg | h1]
__device__ float g_W1[432 * 32];      // [w2_re ; b2_re ; root]
__device__ float g_W2[864 * 64];
__device__ float g_t1[NN * 32];       // elu(conv1) pre-BN
__device__ float g_t2[NN * 64];       // elu(conv2) pre-BN
__device__ float g_bn[256];           // sum1[0:32] sq1[64:96] sum2[128:192] sq2[192:256]

// global software barrier state
__device__ unsigned g_bar_cnt = 0;
__device__ volatile unsigned g_bar_gen = 0;

__device__ __forceinline__ float eluf(float x) { return x > 0.f ? x : expm1f(x); }

// ---- packed f32x2 helpers (Blackwell FFMA2: 2x fp32 throughput) ----
typedef unsigned long long ull;
__device__ __forceinline__ ull pack2(float lo, float hi) {
    ull d; asm("mov.b64 %0, {%1, %2};" : "=l"(d) : "f"(lo), "f"(hi)); return d;
}
__device__ __forceinline__ void unpack2(ull v, float& lo, float& hi) {
    asm("mov.b64 {%0, %1}, %2;" : "=f"(lo), "=f"(hi) : "l"(v));
}
__device__ __forceinline__ ull ffma2(ull a, ull b, ull c) {
    ull d; asm("fma.rn.f32x2 %0, %1, %2, %3;" : "=l"(d) : "l"(a), "l"(b), "l"(c)); return d;
}

// ---- grid-wide barrier (all NBLK blocks resident by construction) ----
__device__ __forceinline__ void gsync() {
    __threadfence();
    __syncthreads();
    if (threadIdx.x == 0) {
        unsigned gen = g_bar_gen;
        if (atomicAdd(&g_bar_cnt, 1u) == (unsigned)(gridDim.x - 1)) {
            g_bar_cnt = 0;
            __threadfence();
            g_bar_gen = gen + 1;
        } else {
            while (g_bar_gen == gen) { __nanosleep(64); }
        }
    }
    __syncthreads();
}

// ---------------- weight-augment prep helper ----------------
template <int CIN, int COUT>
__device__ __forceinline__ void prepW_elem(int idx, const float* __restrict__ w2,
                                           const float* __restrict__ b2,
                                           const float* __restrict__ root,
                                           float* __restrict__ W) {
    constexpr int KA = 25 * CIN + 2 * CIN;
    if (idx >= KA * COUT) return;
    int kidx = idx / COUT, o = idx % COUT;
    float v;
    if (kidx < 25 * CIN) {
        int k = kidx / CIN, i = kidx % CIN;
        v = w2[(k * CIN + i) * COUT + o];
    } else if (kidx < 25 * CIN + CIN) {
        int i = kidx - 25 * CIN;
        v = b2[i * COUT + o];
    } else {
        int i = kidx - 25 * CIN - CIN;
        v = root[i * COUT + o];
    }
    W[idx] = v;
}

// ===== persistent front kernel: init + edgeMLP + deg + prepW + scan + CSR fill =====
__global__ void __launch_bounds__(NTHR) k_front(
        const float* __restrict__ ea, const int* __restrict__ ei,
        const float* __restrict__ w1a, const float* __restrict__ b1a,
        const float* __restrict__ w1b, const float* __restrict__ b1b,
        const float* __restrict__ w2a, const float* __restrict__ b2a, const float* __restrict__ roota,
        const float* __restrict__ w2b, const float* __restrict__ b2b, const float* __restrict__ rootb,
        float* __restrict__ out) {
    int bid = blockIdx.x, t = threadIdx.x;
    int gid = bid * NTHR + t;
    const int GT = NBLK * NTHR;
    __shared__ float sA[225];
    __shared__ float sB[225];
    __shared__ int sscan[256];

    // ---- phase A0: zero deg / bn / out ----
    for (int i = gid; i < NN; i += GT) g_deg[i] = 0;
    if (gid < 256) g_bn[gid] = 0.f;
    if (gid == 0) out[0] = 0.f;
    // load edge-MLP weights while waiting
    for (int l = t; l < 225; l += NTHR) {
        sA[l] = (l < 200) ? w1a[l] : b1a[l - 200];
        sB[l] = (l < 200) ? w1b[l] : b1b[l - 200];
    }
    gsync();

    // ---- phase A1: edge MLP + degree atomics + prepW ----
    for (int e = gid; e < NE; e += GT) {
        atomicAdd(&g_deg[ei[NE + e]], 1);
        float4 a0 = *(const float4*)&ea[e * 8];
        float4 a1 = *(const float4*)&ea[e * 8 + 4];
        float a[8] = {a0.x, a0.y, a0.z, a0.w, a1.x, a1.y, a1.z, a1.w};
        #pragma unroll
        for (int k = 0; k < 25; k++) {
            float s = sA[200 + k];
            #pragma unroll
            for (int i = 0; i < 8; i++) s += a[i] * sA[i * 25 + k];
            g_h1e[e * 25 + k] = fmaxf(s, 0.f);
        }
        #pragma unroll
        for (int k = 0; k < 25; k++) {
            float s = sB[200 + k];
            #pragma unroll
            for (int i = 0; i < 8; i++) s += a[i] * sB[i * 25 + k];
            g_h2e[e * 25 + k] = fmaxf(s, 0.f);
        }
    }
    for (int i = gid; i < 432 * 32; i += GT) prepW_elem<16, 32>(i, w2a, b2a, roota, g_W1);
    for (int i = gid; i < 864 * 64; i += GT) prepW_elem<32, 64>(i, w2b, b2b, rootb, g_W2);
    gsync();

    // ---- phase B1: per-block inclusive scan of its CHUNK of degrees ----
    int base = bid * CHUNK;
    {
        int v = 0;
        if (t < CHUNK && base + t < NN) v = g_deg[base + t];
        sscan[t] = (t < CHUNK) ? v : 0;
        __syncthreads();
        #pragma unroll
        for (int off = 1; off < 128; off <<= 1) {
            int v2 = (t >= off && t < 128) ? sscan[t - off] : 0;
            __syncthreads();
            if (t < 128) sscan[t] += v2;
            __syncthreads();
        }
        if (t == 0) g_part[bid] = sscan[127];
        if (t < CHUNK && base + t < NN) g_offs[base + t] = sscan[t];  // inclusive, chunk-local
    }
    gsync();

    // ---- phase B2: block 0 exclusive-scans the 148 chunk totals ----
    if (bid == 0) {
        int v = (t < NBLK) ? g_part[t] : 0;
        sscan[t] = v;
        __syncthreads();
        #pragma unroll
        for (int off = 1; off < 256; off <<= 1) {
            int v2 = (t >= off) ? sscan[t - off] : 0;
            __syncthreads();
            sscan[t] += v2;
            __syncthreads();
        }
        if (t < NBLK) g_ppre[t] = (t == 0) ? 0 : sscan[t - 1];
    }
    gsync();

    // ---- phase B3: finalize exclusive offsets + cursors ----
    if (t < CHUNK && base + t < NN) {
        int incl = g_offs[base + t];
        int excl = g_ppre[bid] + incl - g_deg[base + t];
        g_offs[base + t] = excl;
        g_cursor[base + t] = excl;
    }
    if (gid == 0) g_offs[NN] = NE;
    gsync();

    // ---- phase C: CSR fill ----
    for (int e = gid; e < NE; e += GT) {
        int d = ei[NE + e];
        int pos = atomicAdd(&g_cursor[d], 1);
        g_csr[pos] = e;
    }
}

// ------- per-node gather of rank-1 outer products; optional fused BN+ELU on features ----
template <int CIN, bool BN>
__global__ void __launch_bounds__(256) k_gather(const int* __restrict__ ei,
                                                const float* __restrict__ xfeat,
                                                const float* __restrict__ hE,
                                                float* __restrict__ A,
                                                const float* __restrict__ gamma,
                                                const float* __restrict__ beta,
                                                const float* __restrict__ bsum,
                                                const float* __restrict__ bsq) {
    constexpr int SW = 25 * CIN;
    constexpr int KA = SW + 2 * CIN;
    constexpr int NACC = (SW + 255) / 256;
    constexpr int EB = 8;
    constexpr int EW = 25 + CIN;
    constexpr int LOADS = EB * EW;
    int n = blockIdx.x;
    int t = threadIdx.x;
    __shared__ float shh[EB][25];
    __shared__ float shx[EB][CIN];
    __shared__ float s_scale[CIN];
    __shared__ float s_shift[CIN];
    if (BN) {
        if (t < CIN) {
            float m = bsum[t] * (1.f / NN);
            float var = bsq[t] * (1.f / NN) - m * m;
            float inv = rsqrtf(var + 1e-5f);
            float sc = inv * gamma[t];
            s_scale[t] = sc;
            s_shift[t] = beta[t] - m * sc;
        }
        __syncthreads();
    }
    float acc[NACC];
    #pragma unroll
    for (int j = 0; j < NACC; j++) acc[j] = 0.f;
    float xs = 0.f;
    int e0 = g_offs[n], e1 = g_offs[n + 1];

    for (int p0 = e0; p0 < e1; p0 += EB) {
        int cnt = e1 - p0; if (cnt > EB) cnt = EB;
        #pragma unroll
        for (int l = t; l < LOADS; l += 256) {
            int j = l / EW, r = l - j * EW;
            float v = 0.f;
            if (j < cnt) {
                int e = __ldg(&g_csr[p0 + j]);
                if (r < 25) v = hE[e * 25 + r];
                else {
                    int c = r - 25;
                    v = xfeat[__ldg(&ei[e]) * CIN + c];
                    if (BN) v = eluf(v * s_scale[c] + s_shift[c]);
                }
            }
            if (r < 25) shh[j][r] = v;
            else        shx[j][r - 25] = v;
        }
        __syncthreads();
        #pragma unroll
        for (int j = 0; j < EB; j++) {
            #pragma unroll
            for (int na = 0; na < NACC; na++) {
                int idx = t + na * 256;
                if (idx < SW) acc[na] += shh[j][idx / CIN] * shx[j][idx % CIN];
            }
        }
        if (t < CIN) {
            #pragma unroll
            for (int j = 0; j < EB; j++) xs += shx[j][t];
        }
        __syncthreads();
    }
    float inv = 1.f / fmaxf((float)(e1 - e0), 1.f);
    #pragma unroll
    for (int na = 0; na < NACC; na++) {
        int idx = t + na * 256;
        if (idx < SW) A[n * KA + idx] = acc[na] * inv;
    }
    if (t < CIN) {
        A[n * KA + SW + t] = xs * inv;
        float sv = xfeat[n * CIN + t];
        if (BN) sv = eluf(sv * s_scale[t] + s_shift[t]);
        A[n * KA + SW + CIN + t] = sv;
    }
}

// ------- dense GEMM  out = elu(A[NN,KA] @ W[KA,COUT] + bias), packed f32x2 FMA -------
// (exact R5 version: BM=64, 256 threads, 4 rows x TC cols per thread)
template <int KA, int COUT, int BK>
__global__ void __launch_bounds__(256) k_gemm(const float* __restrict__ A,
                                              const float* __restrict__ W,
                                              const float* __restrict__ bias,
                                              float* __restrict__ out) {
    constexpr int BM = 64;
    constexpr int TC = COUT / 16;   // cols per thread (2 or 4)
    constexpr int NP = TC / 2;      // f32x2 pairs (1 or 2)
    __shared__ float As[BK][BM];
    __shared__ float Bs[BK * COUT];
    int tid = threadIdx.x;
    int tx = tid & 15, ty = tid >> 4;
    int row0 = blockIdx.x * BM;

    ull acc[4][NP];
    #pragma unroll
    for (int m = 0; m < 4; m++)
        #pragma unroll
        for (int p = 0; p < NP; p++) acc[m][p] = 0ull;

    for (int k0 = 0; k0 < KA; k0 += BK) {
        constexpr int AF4 = BM * BK / 4;
        #pragma unroll
        for (int l = tid; l < AF4; l += 256) {
            int r = l / (BK / 4), q = l % (BK / 4);
            int gr = row0 + r;
            float4 v = make_float4(0.f, 0.f, 0.f, 0.f);
            if (gr < NN) v = *(const float4*)&A[gr * KA + k0 + q * 4];
            As[q * 4 + 0][r] = v.x;
            As[q * 4 + 1][r] = v.y;
            As[q * 4 + 2][r] = v.z;
            As[q * 4 + 3][r] = v.w;
        }
        constexpr int BF4 = BK * COUT / 4;
        const float4* Wp = (const float4*)&W[k0 * COUT];
        #pragma unroll
        for (int l = tid; l < BF4; l += 256) ((float4*)Bs)[l] = Wp[l];
        __syncthreads();

        #pragma unroll
        for (int kk = 0; kk < BK; kk++) {
            ull bp[NP];
            if (NP == 2) {
                float4 bq = *(const float4*)&Bs[kk * COUT + tx * 4];
                bp[0] = pack2(bq.x, bq.y);
                bp[1] = pack2(bq.z, bq.w);
            } else {
                float2 bq = *(const float2*)&Bs[kk * COUT + tx * 2];
                bp[0] = pack2(bq.x, bq.y);
            }
            float4 a4 = *(const float4*)&As[kk][ty * 4];
            ull aa0 = pack2(a4.x, a4.x);
            ull aa1 = pack2(a4.y, a4.y);
            ull aa2 = pack2(a4.z, a4.z);
            ull aa3 = pack2(a4.w, a4.w);
            #pragma unroll
            for (int p = 0; p < NP; p++) {
                acc[0][p] = ffma2(aa0, bp[p], acc[0][p]);
                acc[1][p] = ffma2(aa1, bp[p], acc[1][p]);
                acc[2][p] = ffma2(aa2, bp[p], acc[2][p]);
                acc[3][p] = ffma2(aa3, bp[p], acc[3][p]);
            }
        }
        __syncthreads();
    }
    #pragma unroll
    for (int m = 0; m < 4; m++) {
        int n = row0 + ty * 4 + m;
        if (n >= NN) continue;
        #pragma unroll
        for (int p = 0; p < NP; p++) {
            float lo, hi;
            unpack2(acc[m][p], lo, hi);
            int o = tx * TC + p * 2;
            out[n * COUT + o]     = eluf(lo + bias[o]);
            out[n * COUT + o + 1] = eluf(hi + bias[o + 1]);
        }
    }
}

// ---------------- batchnorm stats (R5 version) ----------------
template <int C>
__global__ void k_bnstats(const float* __restrict__ t, float* __restrict__ sum,
                          float* __restrict__ sq) {
    constexpr int G = 256 / C;
    int tid = threadIdx.x;
    int c = tid % C, g = tid / C;
    float s = 0.f, q = 0.f;
    for (int r = blockIdx.x * G + g; r < NN; r += gridDim.x * G) {
        float v = t[r * C + c];
        s += v;
        q += v * v;
    }
    __shared__ float ss[256], qq[256];
    ss[tid] = s;
    qq[tid] = q;
    __syncthreads();
    if (g == 0) {
        #pragma unroll
        for (int gg = 1; gg < G; gg++) {
            s += ss[gg * C + c];
            q += qq[gg * C + c];
        }
        atomicAdd(&sum[c], s);
        atomicAdd(&sq[c], q);
    }
}

// ---------------- FC head + global sum, fused BN2 finalize+apply ----------------
__global__ void __launch_bounds__(256) k_fc(const float* __restrict__ t2,
                                            const float* __restrict__ w1,
                                            const float* __restrict__ b1,
                                            const float* __restrict__ w2,
                                            const float* __restrict__ b2,
                                            const float* __restrict__ gamma,
                                            const float* __restrict__ beta,
                                            const float* __restrict__ bsum,
                                            const float* __restrict__ bsq,
                                            float* __restrict__ out) {
    __shared__ float sw[64 * 128];
    int tid = threadIdx.x;
    int lane = tid & 31, warp = tid >> 5;
    #pragma unroll
    for (int l = tid; l < 64 * 128 / 4; l += 256)
        ((float4*)sw)[l] = ((const float4*)w1)[l];
    float b1v[4], w2v[4];
    #pragma unroll
    for (int j = 0; j < 4; j++) {
        b1v[j] = b1[j * 32 + lane];
        w2v[j] = w2[j * 32 + lane];
    }
    float b2v = b2[0];
    float scl0, sft0, scl1, sft1;
    {
        float m = bsum[lane] * (1.f / NN);
        float var = bsq[lane] * (1.f / NN) - m * m;
        scl0 = rsqrtf(var + 1e-5f) * gamma[lane];
        sft0 = beta[lane] - m * scl0;
        int c = lane + 32;
        m = bsum[c] * (1.f / NN);
        var = bsq[c] * (1.f / NN) - m * m;
        scl1 = rsqrtf(var + 1e-5f) * gamma[c];
        sft1 = beta[c] - m * scl1;
    }
    __syncthreads();

    float local = 0.f;
    for (int n = blockIdx.x * 8 + warp; n < NN; n += gridDim.x * 8) {
        float hv0 = eluf(t2[n * 64 + lane] * scl0 + sft0);
        float hv1 = eluf(t2[n * 64 + 32 + lane] * scl1 + sft1);
        float s0 = b1v[0], s1 = b1v[1], s2 = b1v[2], s3 = b1v[3];
        #pragma unroll
        for (int i = 0; i < 64; i++) {
            float hv = __shfl_sync(0xffffffffu, (i < 32) ? hv0 : hv1, i & 31);
            s0 += hv * sw[i * 128 + lane];
            s1 += hv * sw[i * 128 + 32 + lane];
            s2 += hv * sw[i * 128 + 64 + lane];
            s3 += hv * sw[i * 128 + 96 + lane];
        }
        float contrib = eluf(s0) * w2v[0] + eluf(s1) * w2v[1]
                      + eluf(s2) * w2v[2] + eluf(s3) * w2v[3];
        #pragma unroll
        for (int off = 16; off > 0; off >>= 1)
            contrib += __shfl_xor_sync(0xffffffffu, contrib, off);
        if (lane == 0) local += eluf(contrib + b2v);
    }
    if (lane == 0) atomicAdd(out, local);
}

// ---------------- launch ----------------
extern "C" void kernel_launch(void* const* d_in, const int* in_sizes, int n_in,
                              void* d_out, int out_size) {
    const float* x        = (const float*)d_in[0];
    const int*   ei       = (const int*)d_in[1];
    const float* ea       = (const float*)d_in[2];
    const float* nn1_w1   = (const float*)d_in[3];
    const float* nn1_b1   = (const float*)d_in[4];
    const float* nn1_w2   = (const float*)d_in[5];
    const float* nn1_b2   = (const float*)d_in[6];
    const float* c1_root  = (const float*)d_in[7];
    const float* c1_bias  = (const float*)d_in[8];
    const float* bn1_g    = (const float*)d_in[9];
    const float* bn1_b    = (const float*)d_in[10];
    const float* nn2_w1   = (const float*)d_in[11];
    const float* nn2_b1   = (const float*)d_in[12];
    const float* nn2_w2   = (const float*)d_in[13];
    const float* nn2_b2   = (const float*)d_in[14];
    const float* c2_root  = (const float*)d_in[15];
    const float* c2_bias  = (const float*)d_in[16];
    const float* bn2_g    = (const float*)d_in[17];
    const float* bn2_b    = (const float*)d_in[18];
    const float* fc1_w    = (const float*)d_in[19];
    const float* fc1_b    = (const float*)d_in[20];
    const float* fc2_w    = (const float*)d_in[21];
    const float* fc2_b    = (const float*)d_in[22];
    float* out = (float*)d_out;

    float *pA1, *pA2, *pW1, *pW2, *ph1e, *ph2e, *pt1, *pt2, *pbn;
    cudaGetSymbolAddress((void**)&pA1, g_A1);
    cudaGetSymbolAddress((void**)&pA2, g_A2);
    cudaGetSymbolAddress((void**)&pW1, g_W1);
    cudaGetSymbolAddress((void**)&pW2, g_W2);
    cudaGetSymbolAddress((void**)&ph1e, g_h1e);
    cudaGetSymbolAddress((void**)&ph2e, g_h2e);
    cudaGetSymbolAddress((void**)&pt1, g_t1);
    cudaGetSymbolAddress((void**)&pt2, g_t2);
    cudaGetSymbolAddress((void**)&pbn, g_bn);

    // 1: fused front-end (init + edgeMLP/deg/prepW + 2-level scan + CSR fill)
    k_front<<<NBLK, NTHR>>>(ea, ei, nn1_w1, nn1_b1, nn2_w1, nn2_b1,
                            nn1_w2, nn1_b2, c1_root, nn2_w2, nn2_b2, c2_root, out);

    // 2-4: conv1
    k_gather<16, false><<<NN, 256>>>(ei, x, ph1e, pA1, nullptr, nullptr, nullptr, nullptr);
    k_gemm<432, 32, 16><<<(NN + 63) / 64, 256>>>(pA1, pW1, c1_bias, pt1);
    k_bnstats<32><<<64, 256>>>(pt1, pbn + 0, pbn + 64);

    // 5-7: conv2 (gather applies BN1+ELU on the fly)
    k_gather<32, true><<<NN, 256>>>(ei, pt1, ph2e, pA2, bn1_g, bn1_b, pbn + 0, pbn + 64);
    k_gemm<864, 64, 32><<<(NN + 63) / 64, 256>>>(pA2, pW2, c2_bias, pt2);
    k_bnstats<64><<<64, 256>>>(pt2, pbn + 128, pbn + 192);

    // 8: head (BN2 finalize+apply + fc1 + fc2 + global sum)
    k_fc<<<148, 256>>>(pt2, fc1_w, fc1_b, fc2_w, fc2_b,
                       bn2_g, bn2_b, pbn + 128, pbn + 192, out);
}

// round 8
// speedup vs baseline: 1.4002x; 1.2209x over previous
#include <cuda_runtime.h>
#include <cuda_bf16.h>

#define NN 10000
#define NE 80000

// ---------------- scratch (static device memory, no allocs) ----------------
__device__ int   g_deg[NN];
__device__ int   g_offs[NN + 1];
__device__ int   g_cursor[NN];
__device__ int   g_csr[NE];
__device__ float g_h1e[NE * 25];      // relu(ea@nn1_w1+b1)
__device__ float g_h2e[NE * 25];      // relu(ea@nn2_w1+b2_1)
__device__ float g_A1[NN * 432];      // [S1/deg | Xsum1/deg | x]
__device__ float g_A2[NN * 864];      // [S2/deg | Hsum/deg | h1]
__device__ float g_W1[432 * 32];      // [w2_re ; b2_re ; root]
__device__ float g_W2[864 * 64];
__device__ float g_t1[NN * 32];       // elu(conv1) pre-BN
__device__ float g_h1[NN * 32];       // elu(bn1(t1))
__device__ float g_t2[NN * 64];       // elu(conv2) pre-BN
__device__ float g_bn[256];           // sum1[0:32] sq1[64:96] sum2[128:192] sq2[192:256]

__device__ __forceinline__ float eluf(float x) { return x > 0.f ? x : expm1f(x); }

// ---- packed f32x2 helpers (Blackwell FFMA2: 2x fp32 throughput) ----
typedef unsigned long long ull;
__device__ __forceinline__ ull pack2(float lo, float hi) {
    ull d; asm("mov.b64 %0, {%1, %2};" : "=l"(d) : "f"(lo), "f"(hi)); return d;
}
__device__ __forceinline__ void unpack2(ull v, float& lo, float& hi) {
    asm("mov.b64 {%0, %1}, %2;" : "=f"(lo), "=f"(hi) : "l"(v));
}
__device__ __forceinline__ ull ffma2(ull a, ull b, ull c) {
    ull d; asm("fma.rn.f32x2 %0, %1, %2, %3;" : "=l"(d) : "l"(a), "l"(b), "l"(c)); return d;
}

// ---------------- init ----------------
__global__ void k_init(float* out) {
    int i = blockIdx.x * blockDim.x + threadIdx.x;
    if (i < NN) g_deg[i] = 0;
    if (i < 256) g_bn[i] = 0.f;
    if (i == 0) out[0] = 0.f;
}

// ---------------- degree histogram ----------------
__global__ void k_deg(const int* __restrict__ ei) {
    int e = blockIdx.x * blockDim.x + threadIdx.x;
    if (e < NE) atomicAdd(&g_deg[ei[NE + e]], 1);
}

// ---------------- exclusive scan over 10000 degrees (single block) ----------------
__global__ void k_scan() {
    __shared__ int part[1024];
    int t = threadIdx.x;
    int base = t * 10;
    int s = 0;
    if (base < NN) {
        #pragma unroll
        for (int j = 0; j < 10; j++) if (base + j < NN) s += g_deg[base + j];
    }
    part[t] = s;
    __syncthreads();
    for (int off = 1; off < 1024; off <<= 1) {
        int v = 0;
        if (t >= off) v = part[t - off];
        __syncthreads();
        part[t] += v;
        __syncthreads();
    }
    int excl = (t == 0) ? 0 : part[t - 1];
    if (base < NN) {
        int run = excl;
        #pragma unroll
        for (int j = 0; j < 10; j++) {
            if (base + j < NN) {
                g_offs[base + j] = run;
                g_cursor[base + j] = run;
                run += g_deg[base + j];
            }
        }
    }
    if (t == 1023) g_offs[NN] = part[1023];
}

// ---------------- CSR fill ----------------
__global__ void k_fill(const int* __restrict__ ei) {
    int e = blockIdx.x * blockDim.x + threadIdx.x;
    if (e < NE) {
        int d = ei[NE + e];
        int pos = atomicAdd(&g_cursor[d], 1);
        g_csr[pos] = e;
    }
}

// ---------------- fused edge MLP hidden layers (both convs) ----------------
__global__ void k_edgemlp(const float* __restrict__ ea,
                          const float* __restrict__ w1a, const float* __restrict__ b1a,
                          const float* __restrict__ w1b, const float* __restrict__ b1b) {
    __shared__ float sA[225];
    __shared__ float sB[225];
    int tid = threadIdx.x;
    for (int l = tid; l < 225; l += blockDim.x) {
        sA[l] = (l < 200) ? w1a[l] : b1a[l - 200];
        sB[l] = (l < 200) ? w1b[l] : b1b[l - 200];
    }
    __syncthreads();
    int e = blockIdx.x * blockDim.x + tid;
    if (e >= NE) return;
    float4 a0 = *(const float4*)&ea[e * 8];
    float4 a1 = *(const float4*)&ea[e * 8 + 4];
    float a[8] = {a0.x, a0.y, a0.z, a0.w, a1.x, a1.y, a1.z, a1.w};
    #pragma unroll
    for (int k = 0; k < 25; k++) {
        float s = sA[200 + k];
        #pragma unroll
        for (int i = 0; i < 8; i++) s += a[i] * sA[i * 25 + k];
        g_h1e[e * 25 + k] = fmaxf(s, 0.f);
    }
    #pragma unroll
    for (int k = 0; k < 25; k++) {
        float s = sB[200 + k];
        #pragma unroll
        for (int i = 0; i < 8; i++) s += a[i] * sB[i * 25 + k];
        g_h2e[e * 25 + k] = fmaxf(s, 0.f);
    }
}

// ---------------- build augmented weight matrix [25*CIN + 2*CIN, COUT] ----------------
template <int CIN, int COUT>
__global__ void k_prepW(const float* __restrict__ w2, const float* __restrict__ b2,
                        const float* __restrict__ root, float* __restrict__ W) {
    constexpr int KA = 25 * CIN + 2 * CIN;
    int idx = blockIdx.x * blockDim.x + threadIdx.x;
    if (idx >= KA * COUT) return;
    int kidx = idx / COUT, o = idx % COUT;
    float v;
    if (kidx < 25 * CIN) {
        int k = kidx / CIN, i = kidx % CIN;
        v = w2[(k * CIN + i) * COUT + o];
    } else if (kidx < 25 * CIN + CIN) {
        int i = kidx - 25 * CIN;
        v = b2[i * COUT + o];
    } else {
        int i = kidx - 25 * CIN - CIN;
        v = root[i * COUT + o];
    }
    W[idx] = v;
}

// ------- per-node gather of rank-1 outer products, batched edges (EB per barrier) ----
template <int CIN>
__global__ void __launch_bounds__(256) k_gather(const int* __restrict__ ei,
                                                const float* __restrict__ xfeat,
                                                const float* __restrict__ hE,
                                                float* __restrict__ A) {
    constexpr int SW = 25 * CIN;
    constexpr int KA = SW + 2 * CIN;
    constexpr int NACC = (SW + 255) / 256;
    constexpr int EB = 16;
    constexpr int EW = 25 + CIN;
    constexpr int LOADS = EB * EW;
    int n = blockIdx.x;
    int t = threadIdx.x;
    __shared__ float shh[EB][25];
    __shared__ float shx[EB][CIN];
    float acc[NACC];
    #pragma unroll
    for (int j = 0; j < NACC; j++) acc[j] = 0.f;
    float xs = 0.f;
    int e0 = g_offs[n], e1 = g_offs[n + 1];

    for (int p0 = e0; p0 < e1; p0 += EB) {
        int cnt = e1 - p0; if (cnt > EB) cnt = EB;
        #pragma unroll
        for (int l = t; l < LOADS; l += 256) {
            int j = l / EW, r = l - j * EW;
            float v = 0.f;
            if (j < cnt) {
                int e = __ldg(&g_csr[p0 + j]);
                if (r < 25) v = hE[e * 25 + r];
                else        v = xfeat[__ldg(&ei[e]) * CIN + (r - 25)];
            }
            if (r < 25) shh[j][r] = v;
            else        shx[j][r - 25] = v;
        }
        __syncthreads();
        #pragma unroll
        for (int j = 0; j < EB; j++) {
            #pragma unroll
            for (int na = 0; na < NACC; na++) {
                int idx = t + na * 256;
                if (idx < SW) acc[na] += shh[j][idx / CIN] * shx[j][idx % CIN];
            }
        }
        if (t < CIN) {
            #pragma unroll
            for (int j = 0; j < EB; j++) xs += shx[j][t];
        }
        __syncthreads();
    }
    float inv = 1.f / fmaxf((float)(e1 - e0), 1.f);
    #pragma unroll
    for (int na = 0; na < NACC; na++) {
        int idx = t + na * 256;
        if (idx < SW) A[n * KA + idx] = acc[na] * inv;
    }
    if (t < CIN) {
        A[n * KA + SW + t] = xs * inv;
        A[n * KA + SW + CIN + t] = xfeat[n * CIN + t];
    }
}

// ------- dense GEMM  out = elu(A[NN,KA] @ W[KA,COUT] + bias), packed f32x2 FMA -------
// R5-proven inner loop (BM=64, 256 thr, 4 rows x TC cols) + fused BN-stat epilogue.
template <int KA, int COUT, int BK>
__global__ void __launch_bounds__(256) k_gemm(const float* __restrict__ A,
                                              const float* __restrict__ W,
                                              const float* __restrict__ bias,
                                              float* __restrict__ out,
                                              float* __restrict__ bnsum,
                                              float* __restrict__ bnsq) {
    constexpr int BM = 64;
    constexpr int TC = COUT / 16;   // cols per thread (2 or 4)
    constexpr int NP = TC / 2;      // f32x2 pairs (1 or 2)
    __shared__ float As[BK][BM];
    __shared__ float Bs[BK * COUT];
    int tid = threadIdx.x;
    int tx = tid & 15, ty = tid >> 4;
    int row0 = blockIdx.x * BM;

    ull acc[4][NP];
    #pragma unroll
    for (int m = 0; m < 4; m++)
        #pragma unroll
        for (int p = 0; p < NP; p++) acc[m][p] = 0ull;

    for (int k0 = 0; k0 < KA; k0 += BK) {
        constexpr int AF4 = BM * BK / 4;
        #pragma unroll
        for (int l = tid; l < AF4; l += 256) {
            int r = l / (BK / 4), q = l % (BK / 4);
            int gr = row0 + r;
            float4 v = make_float4(0.f, 0.f, 0.f, 0.f);
            if (gr < NN) v = *(const float4*)&A[gr * KA + k0 + q * 4];
            As[q * 4 + 0][r] = v.x;
            As[q * 4 + 1][r] = v.y;
            As[q * 4 + 2][r] = v.z;
            As[q * 4 + 3][r] = v.w;
        }
        constexpr int BF4 = BK * COUT / 4;
        const float4* Wp = (const float4*)&W[k0 * COUT];
        #pragma unroll
        for (int l = tid; l < BF4; l += 256) ((float4*)Bs)[l] = Wp[l];
        __syncthreads();

        #pragma unroll
        for (int kk = 0; kk < BK; kk++) {
            ull bp[NP];
            if (NP == 2) {
                float4 bq = *(const float4*)&Bs[kk * COUT + tx * 4];
                bp[0] = pack2(bq.x, bq.y);
                bp[1] = pack2(bq.z, bq.w);
            } else {
                float2 bq = *(const float2*)&Bs[kk * COUT + tx * 2];
                bp[0] = pack2(bq.x, bq.y);
            }
            float4 a4 = *(const float4*)&As[kk][ty * 4];
            ull aa0 = pack2(a4.x, a4.x);
            ull aa1 = pack2(a4.y, a4.y);
            ull aa2 = pack2(a4.z, a4.z);
            ull aa3 = pack2(a4.w, a4.w);
            #pragma unroll
            for (int p = 0; p < NP; p++) {
                acc[0][p] = ffma2(aa0, bp[p], acc[0][p]);
                acc[1][p] = ffma2(aa1, bp[p], acc[1][p]);
                acc[2][p] = ffma2(aa2, bp[p], acc[2][p]);
                acc[3][p] = ffma2(aa3, bp[p], acc[3][p]);
            }
        }
        __syncthreads();
    }

    // epilogue: bias + ELU + store, accumulating per-thread column stats
    float colsum[TC], colsq[TC];
    #pragma unroll
    for (int j = 0; j < TC; j++) { colsum[j] = 0.f; colsq[j] = 0.f; }
    #pragma unroll
    for (int m = 0; m < 4; m++) {
        int n = row0 + ty * 4 + m;
        bool valid = (n < NN);
        #pragma unroll
        for (int p = 0; p < NP; p++) {
            float lo, hi;
            unpack2(acc[m][p], lo, hi);
            int o = tx * TC + p * 2;
            float v0 = eluf(lo + bias[o]);
            float v1 = eluf(hi + bias[o + 1]);
            if (valid) {
                out[n * COUT + o]     = v0;
                out[n * COUT + o + 1] = v1;
                colsum[p * 2]     += v0;
                colsq[p * 2]      += v0 * v0;
                colsum[p * 2 + 1] += v1;
                colsq[p * 2 + 1]  += v1 * v1;
            }
        }
    }
    // reuse As/Bs smem for 16-way column reduce (16 ty-groups per column)
    float* Rs = &As[0][0];   // >= 16*COUT floats
    float* Rq = &Bs[0];      // >= 16*COUT floats
    #pragma unroll
    for (int j = 0; j < TC; j++) {
        int o = tx * TC + j;
        Rs[o * 16 + ty] = colsum[j];
        Rq[o * 16 + ty] = colsq[j];
    }
    __syncthreads();
    if (tid < COUT) {
        float s = 0.f, q = 0.f;
        #pragma unroll
        for (int r = 0; r < 16; r++) { s += Rs[tid * 16 + r]; q += Rq[tid * 16 + r]; }
        atomicAdd(&bnsum[tid], s);
        atomicAdd(&bnsq[tid], q);
    }
}

// ---------------- BN finalize + apply + ELU (fused) ----------------
template <int C>
__global__ void k_bnapply(const float* __restrict__ t, float* __restrict__ h,
                          const float* __restrict__ gamma, const float* __restrict__ beta,
                          const float* __restrict__ bsum, const float* __restrict__ bsq) {
    __shared__ float sscale[C], sshift[C];
    int tid = threadIdx.x;
    if (tid < C) {
        float m = bsum[tid] * (1.f / NN);
        float var = bsq[tid] * (1.f / NN) - m * m;
        float sc = rsqrtf(var + 1e-5f) * gamma[tid];
        sscale[tid] = sc;
        sshift[tid] = beta[tid] - m * sc;
    }
    __syncthreads();
    int idx = blockIdx.x * blockDim.x + tid;
    if (idx < NN * C) {
        int c = idx % C;
        h[idx] = eluf(t[idx] * sscale[c] + sshift[c]);
    }
}

// ---------------- FC head + global sum, fused BN2 finalize+apply ----------------
__global__ void __launch_bounds__(256) k_fc(const float* __restrict__ t2,
                                            const float* __restrict__ w1,
                                            const float* __restrict__ b1,
                                            const float* __restrict__ w2,
                                            const float* __restrict__ b2,
                                            const float* __restrict__ gamma,
                                            const float* __restrict__ beta,
                                            const float* __restrict__ bsum,
                                            const float* __restrict__ bsq,
                                            float* __restrict__ out) {
    __shared__ float sw[64 * 128];
    int tid = threadIdx.x;
    int lane = tid & 31, warp = tid >> 5;
    #pragma unroll
    for (int l = tid; l < 64 * 128 / 4; l += 256)
        ((float4*)sw)[l] = ((const float4*)w1)[l];
    float b1v[4], w2v[4];
    #pragma unroll
    for (int j = 0; j < 4; j++) {
        b1v[j] = b1[j * 32 + lane];
        w2v[j] = w2[j * 32 + lane];
    }
    float b2v = b2[0];
    float scl0, sft0, scl1, sft1;
    {
        float m = bsum[lane] * (1.f / NN);
        float var = bsq[lane] * (1.f / NN) - m * m;
        scl0 = rsqrtf(var + 1e-5f) * gamma[lane];
        sft0 = beta[lane] - m * scl0;
        int c = lane + 32;
        m = bsum[c] * (1.f / NN);
        var = bsq[c] * (1.f / NN) - m * m;
        scl1 = rsqrtf(var + 1e-5f) * gamma[c];
        sft1 = beta[c] - m * scl1;
    }
    __syncthreads();

    float local = 0.f;
    for (int n = blockIdx.x * 8 + warp; n < NN; n += gridDim.x * 8) {
        float hv0 = eluf(t2[n * 64 + lane] * scl0 + sft0);
        float hv1 = eluf(t2[n * 64 + 32 + lane] * scl1 + sft1);
        float s0 = b1v[0], s1 = b1v[1], s2 = b1v[2], s3 = b1v[3];
        #pragma unroll
        for (int i = 0; i < 64; i++) {
            float hv = __shfl_sync(0xffffffffu, (i < 32) ? hv0 : hv1, i & 31);
            s0 += hv * sw[i * 128 + lane];
            s1 += hv * sw[i * 128 + 32 + lane];
            s2 += hv * sw[i * 128 + 64 + lane];
            s3 += hv * sw[i * 128 + 96 + lane];
        }
        float contrib = eluf(s0) * w2v[0] + eluf(s1) * w2v[1]
                      + eluf(s2) * w2v[2] + eluf(s3) * w2v[3];
        #pragma unroll
        for (int off = 16; off > 0; off >>= 1)
            contrib += __shfl_xor_sync(0xffffffffu, contrib, off);
        if (lane == 0) local += eluf(contrib + b2v);
    }
    if (lane == 0) atomicAdd(out, local);
}

// ---------------- launch ----------------
extern "C" void kernel_launch(void* const* d_in, const int* in_sizes, int n_in,
                              void* d_out, int out_size) {
    const float* x        = (const float*)d_in[0];
    const int*   ei       = (const int*)d_in[1];
    const float* ea       = (const float*)d_in[2];
    const float* nn1_w1   = (const float*)d_in[3];
    const float* nn1_b1   = (const float*)d_in[4];
    const float* nn1_w2   = (const float*)d_in[5];
    const float* nn1_b2   = (const float*)d_in[6];
    const float* c1_root  = (const float*)d_in[7];
    const float* c1_bias  = (const float*)d_in[8];
    const float* bn1_g    = (const float*)d_in[9];
    const float* bn1_b    = (const float*)d_in[10];
    const float* nn2_w1   = (const float*)d_in[11];
    const float* nn2_b1   = (const float*)d_in[12];
    const float* nn2_w2   = (const float*)d_in[13];
    const float* nn2_b2   = (const float*)d_in[14];
    const float* c2_root  = (const float*)d_in[15];
    const float* c2_bias  = (const float*)d_in[16];
    const float* bn2_g    = (const float*)d_in[17];
    const float* bn2_b    = (const float*)d_in[18];
    const float* fc1_w    = (const float*)d_in[19];
    const float* fc1_b    = (const float*)d_in[20];
    const float* fc2_w    = (const float*)d_in[21];
    const float* fc2_b    = (const float*)d_in[22];
    float* out = (float*)d_out;

    float *pA1, *pA2, *pW1, *pW2, *ph1e, *ph2e, *pt1, *ph1, *pt2, *pbn;
    cudaGetSymbolAddress((void**)&pA1, g_A1);
    cudaGetSymbolAddress((void**)&pA2, g_A2);
    cudaGetSymbolAddress((void**)&pW1, g_W1);
    cudaGetSymbolAddress((void**)&pW2, g_W2);
    cudaGetSymbolAddress((void**)&ph1e, g_h1e);
    cudaGetSymbolAddress((void**)&ph2e, g_h2e);
    cudaGetSymbolAddress((void**)&pt1, g_t1);
    cudaGetSymbolAddress((void**)&ph1, g_h1);
    cudaGetSymbolAddress((void**)&pt2, g_t2);
    cudaGetSymbolAddress((void**)&pbn, g_bn);

    k_init<<<40, 256>>>(out);
    k_deg<<<313, 256>>>(ei);
    k_scan<<<1, 1024>>>();
    k_fill<<<313, 256>>>(ei);
    k_edgemlp<<<313, 256>>>(ea, nn1_w1, nn1_b1, nn2_w1, nn2_b1);
    k_prepW<16, 32><<<54, 256>>>(nn1_w2, nn1_b2, c1_root, pW1);
    k_prepW<32, 64><<<216, 256>>>(nn2_w2, nn2_b2, c2_root, pW2);

    // conv1: gather -> gemm (+bn1 stats fused) -> bnapply (finalize fused)
    k_gather<16><<<NN, 256>>>(ei, x, ph1e, pA1);
    k_gemm<432, 32, 16><<<(NN + 63) / 64, 256>>>(pA1, pW1, c1_bias, pt1, pbn + 0, pbn + 64);
    k_bnapply<32><<<(NN * 32 + 255) / 256, 256>>>(pt1, ph1, bn1_g, bn1_b, pbn + 0, pbn + 64);

    // conv2: gather -> gemm (+bn2 stats fused)
    k_gather<32><<<NN, 256>>>(ei, ph1, ph2e, pA2);
    k_gemm<864, 64, 32><<<(NN + 63) / 64, 256>>>(pA2, pW2, c2_bias, pt2, pbn + 128, pbn + 192);

    // head: BN2 finalize+apply fused into fc
    k_fc<<<148, 256>>>(pt2, fc1_w, fc1_b, fc2_w, fc2_b,
                       bn2_g, bn2_b, pbn + 128, pbn + 192, out);
}

// round 13
// speedup vs baseline: 1.6932x; 1.2093x over previous
#include <cuda_runtime.h>
#include <cuda_bf16.h>

#define NN 10000
#define NE 80000

// ---------------- scratch (static device memory, no allocs) ----------------
__device__ int   g_deg[NN];
__device__ int   g_offs[NN + 1];
__device__ int   g_cursor[NN];
__device__ int   g_csr[NE];
__device__ float g_h1e[NE * 25];      // relu(ea@nn1_w1+b1)
__device__ float g_h2e[NE * 25];      // relu(ea@nn2_w1+b2_1)
__device__ float g_A1[NN * 432];      // [S1/deg | Xsum1/deg | x]
__device__ float g_A2[NN * 864];      // [S2/deg | Hsum/deg | h1]
__device__ float g_W1[432 * 32];      // [w2_re ; b2_re ; root]
__device__ float g_W2[864 * 64];
__device__ float g_t1[NN * 32];       // elu(conv1) pre-BN
__device__ float g_h1[NN * 32];       // elu(bn1(t1))
__device__ float g_t2[NN * 64];       // elu(conv2) pre-BN
__device__ float g_bn[256];           // sum1[0:32] sq1[64:96] sum2[128:192] sq2[192:256]

__device__ __forceinline__ float eluf(float x) { return x > 0.f ? x : expm1f(x); }

// ---- packed f32x2 helpers (Blackwell FFMA2: 2x fp32 throughput) ----
typedef unsigned long long ull;
__device__ __forceinline__ ull pack2(float lo, float hi) {
    ull d; asm("mov.b64 %0, {%1, %2};" : "=l"(d) : "f"(lo), "f"(hi)); return d;
}
__device__ __forceinline__ void unpack2(ull v, float& lo, float& hi) {
    asm("mov.b64 {%0, %1}, %2;" : "=f"(lo), "=f"(hi) : "l"(v));
}
__device__ __forceinline__ ull ffma2(ull a, ull b, ull c) {
    ull d; asm("fma.rn.f32x2 %0, %1, %2, %3;" : "=l"(d) : "l"(a), "l"(b), "l"(c)); return d;
}

// ---------------- init ----------------
__global__ void k_init(float* out) {
    int i = blockIdx.x * blockDim.x + threadIdx.x;
    if (i < NN) g_deg[i] = 0;
    if (i < 256) g_bn[i] = 0.f;
    if (i == 0) out[0] = 0.f;
}

// ---------------- fused edge MLP (both convs) + degree histogram ----------------
__global__ void k_edgemlp(const float* __restrict__ ea, const int* __restrict__ ei,
                          const float* __restrict__ w1a, const float* __restrict__ b1a,
                          const float* __restrict__ w1b, const float* __restrict__ b1b) {
    __shared__ float sA[225];
    __shared__ float sB[225];
    int tid = threadIdx.x;
    for (int l = tid; l < 225; l += blockDim.x) {
        sA[l] = (l < 200) ? w1a[l] : b1a[l - 200];
        sB[l] = (l < 200) ? w1b[l] : b1b[l - 200];
    }
    __syncthreads();
    int e = blockIdx.x * blockDim.x + tid;
    if (e >= NE) return;
    atomicAdd(&g_deg[ei[NE + e]], 1);
    float4 a0 = *(const float4*)&ea[e * 8];
    float4 a1 = *(const float4*)&ea[e * 8 + 4];
    float a[8] = {a0.x, a0.y, a0.z, a0.w, a1.x, a1.y, a1.z, a1.w};
    #pragma unroll
    for (int k = 0; k < 25; k++) {
        float s = sA[200 + k];
        #pragma unroll
        for (int i = 0; i < 8; i++) s += a[i] * sA[i * 25 + k];
        g_h1e[e * 25 + k] = fmaxf(s, 0.f);
    }
    #pragma unroll
    for (int k = 0; k < 25; k++) {
        float s = sB[200 + k];
        #pragma unroll
        for (int i = 0; i < 8; i++) s += a[i] * sB[i * 25 + k];
        g_h2e[e * 25 + k] = fmaxf(s, 0.f);
    }
}

// ---------------- exclusive scan over 10000 degrees (single block) ----------------
__global__ void k_scan() {
    __shared__ int part[1024];
    int t = threadIdx.x;
    int base = t * 10;
    int s = 0;
    if (base < NN) {
        #pragma unroll
        for (int j = 0; j < 10; j++) if (base + j < NN) s += g_deg[base + j];
    }
    part[t] = s;
    __syncthreads();
    for (int off = 1; off < 1024; off <<= 1) {
        int v = 0;
        if (t >= off) v = part[t - off];
        __syncthreads();
        part[t] += v;
        __syncthreads();
    }
    int excl = (t == 0) ? 0 : part[t - 1];
    if (base < NN) {
        int run = excl;
        #pragma unroll
        for (int j = 0; j < 10; j++) {
            if (base + j < NN) {
                g_offs[base + j] = run;
                g_cursor[base + j] = run;
                run += g_deg[base + j];
            }
        }
    }
    if (t == 1023) g_offs[NN] = part[1023];
}

// ---------------- CSR fill ----------------
__global__ void k_fill(const int* __restrict__ ei) {
    int e = blockIdx.x * blockDim.x + threadIdx.x;
    if (e < NE) {
        int d = ei[NE + e];
        int pos = atomicAdd(&g_cursor[d], 1);
        g_csr[pos] = e;
    }
}

// ---------------- build both augmented weight matrices (one launch, grid split) ------
template <int CIN, int COUT>
__device__ __forceinline__ void prepW_elem(int idx, const float* __restrict__ w2,
                                           const float* __restrict__ b2,
                                           const float* __restrict__ root,
                                           float* __restrict__ W) {
    constexpr int KA = 25 * CIN + 2 * CIN;
    if (idx >= KA * COUT) return;
    int kidx = idx / COUT, o = idx % COUT;
    float v;
    if (kidx < 25 * CIN) {
        int k = kidx / CIN, i = kidx % CIN;
        v = w2[(k * CIN + i) * COUT + o];
    } else if (kidx < 25 * CIN + CIN) {
        int i = kidx - 25 * CIN;
        v = b2[i * COUT + o];
    } else {
        int i = kidx - 25 * CIN - CIN;
        v = root[i * COUT + o];
    }
    W[idx] = v;
}

__global__ void k_prepW(const float* __restrict__ w2a, const float* __restrict__ b2a,
                        const float* __restrict__ roota,
                        const float* __restrict__ w2b, const float* __restrict__ b2b,
                        const float* __restrict__ rootb) {
    int bid = blockIdx.x;
    if (bid < 54) prepW_elem<16, 32>(bid * 256 + threadIdx.x, w2a, b2a, roota, g_W1);
    else          prepW_elem<32, 64>((bid - 54) * 256 + threadIdx.x, w2b, b2b, rootb, g_W2);
}

// ------- warp-per-node gather of rank-1 outer products (no barriers, no smem) -------
// CIN=32: lane = column i; acc[k] (k=0..24) accumulates h[k]*x[i] via shfl broadcast.
__global__ void __launch_bounds__(256) k_gather32(const int* __restrict__ ei,
                                                  const float* __restrict__ xfeat,
                                                  const float* __restrict__ hE,
                                                  float* __restrict__ A) {
    constexpr int KA = 864;
    int lane = threadIdx.x & 31, warp = threadIdx.x >> 5;
    for (int n = blockIdx.x * 8 + warp; n < NN; n += gridDim.x * 8) {
        int e0 = g_offs[n], e1 = g_offs[n + 1];
        float acc[25];
        #pragma unroll
        for (int k = 0; k < 25; k++) acc[k] = 0.f;
        float xs = 0.f;
        for (int p = e0; p < e1; p++) {
            int e = __ldg(&g_csr[p]);
            int src = __ldg(&ei[e]);
            float h = (lane < 25) ? hE[e * 25 + lane] : 0.f;
            float xv = xfeat[src * 32 + lane];
            #pragma unroll
            for (int k = 0; k < 25; k++)
                acc[k] += __shfl_sync(0xffffffffu, h, k) * xv;
            xs += xv;
        }
        float inv = 1.f / fmaxf((float)(e1 - e0), 1.f);
        float* An = &A[n * KA];
        #pragma unroll
        for (int k = 0; k < 25; k++) An[k * 32 + lane] = acc[k] * inv;
        An[800 + lane] = xs * inv;
        An[832 + lane] = xfeat[n * 32 + lane];
    }
}

// CIN=16: half-warps split k-range (lanes 0-15: k=0..12, lanes 16-31: k=13..24).
__global__ void __launch_bounds__(256) k_gather16(const int* __restrict__ ei,
                                                  const float* __restrict__ xfeat,
                                                  const float* __restrict__ hE,
                                                  float* __restrict__ A) {
    constexpr int KA = 432;
    int lane = threadIdx.x & 31, warp = threadIdx.x >> 5;
    int col = lane & 15;
    int kbase = (lane >> 4) * 13;   // 0 or 13
    for (int n = blockIdx.x * 8 + warp; n < NN; n += gridDim.x * 8) {
        int e0 = g_offs[n], e1 = g_offs[n + 1];
        float acc[13];
        #pragma unroll
        for (int j = 0; j < 13; j++) acc[j] = 0.f;
        float xs = 0.f;
        for (int p = e0; p < e1; p++) {
            int e = __ldg(&g_csr[p]);
            int src = __ldg(&ei[e]);
            float h = (lane < 25) ? hE[e * 25 + lane] : 0.f;
            float xv = xfeat[src * 16 + col];
            #pragma unroll
            for (int j = 0; j < 13; j++) {
                int k = kbase + j;
                float hk = __shfl_sync(0xffffffffu, h, k < 25 ? k : 0);
                if (k < 25) acc[j] += hk * xv;
            }
            xs += xv;
        }
        float inv = 1.f / fmaxf((float)(e1 - e0), 1.f);
        float* An = &A[n * KA];
        #pragma unroll
        for (int j = 0; j < 13; j++) {
            int k = kbase + j;
            if (k < 25) An[k * 16 + col] = acc[j] * inv;
        }
        if (lane < 16) {
            An[400 + lane] = xs * inv;
            An[416 + lane] = xfeat[n * 16 + lane];
        }
    }
}

// ------- dense GEMM  out = elu(A[NN,KA] @ W[KA,COUT] + bias), packed f32x2 FMA -------
// R5-proven inner loop (BM=64, 256 thr, 4 rows x TC cols) + fused BN-stat epilogue.
template <int KA, int COUT, int BK>
__global__ void __launch_bounds__(256) k_gemm(const float* __restrict__ A,
                                              const float* __restrict__ W,
                                              const float* __restrict__ bias,
                                              float* __restrict__ out,
                                              float* __restrict__ bnsum,
                                              float* __restrict__ bnsq) {
    constexpr int BM = 64;
    constexpr int TC = COUT / 16;   // cols per thread (2 or 4)
    constexpr int NP = TC / 2;      // f32x2 pairs (1 or 2)
    __shared__ float As[BK][BM];
    __shared__ float Bs[BK * COUT];
    int tid = threadIdx.x;
    int tx = tid & 15, ty = tid >> 4;
    int row0 = blockIdx.x * BM;

    ull acc[4][NP];
    #pragma unroll
    for (int m = 0; m < 4; m++)
        #pragma unroll
        for (int p = 0; p < NP; p++) acc[m][p] = 0ull;

    for (int k0 = 0; k0 < KA; k0 += BK) {
        constexpr int AF4 = BM * BK / 4;
        #pragma unroll
        for (int l = tid; l < AF4; l += 256) {
            int r = l / (BK / 4), q = l % (BK / 4);
            int gr = row0 + r;
            float4 v = make_float4(0.f, 0.f, 0.f, 0.f);
            if (gr < NN) v = *(const float4*)&A[gr * KA + k0 + q * 4];
            As[q * 4 + 0][r] = v.x;
            As[q * 4 + 1][r] = v.y;
            As[q * 4 + 2][r] = v.z;
            As[q * 4 + 3][r] = v.w;
        }
        constexpr int BF4 = BK * COUT / 4;
        const float4* Wp = (const float4*)&W[k0 * COUT];
        #pragma unroll
        for (int l = tid; l < BF4; l += 256) ((float4*)Bs)[l] = Wp[l];
        __syncthreads();

        #pragma unroll
        for (int kk = 0; kk < BK; kk++) {
            ull bp[NP];
            if (NP == 2) {
                float4 bq = *(const float4*)&Bs[kk * COUT + tx * 4];
                bp[0] = pack2(bq.x, bq.y);
                bp[1] = pack2(bq.z, bq.w);
            } else {
                float2 bq = *(const float2*)&Bs[kk * COUT + tx * 2];
                bp[0] = pack2(bq.x, bq.y);
            }
            float4 a4 = *(const float4*)&As[kk][ty * 4];
            ull aa0 = pack2(a4.x, a4.x);
            ull aa1 = pack2(a4.y, a4.y);
            ull aa2 = pack2(a4.z, a4.z);
            ull aa3 = pack2(a4.w, a4.w);
            #pragma unroll
            for (int p = 0; p < NP; p++) {
                acc[0][p] = ffma2(aa0, bp[p], acc[0][p]);
                acc[1][p] = ffma2(aa1, bp[p], acc[1][p]);
                acc[2][p] = ffma2(aa2, bp[p], acc[2][p]);
                acc[3][p] = ffma2(aa3, bp[p], acc[3][p]);
            }
        }
        __syncthreads();
    }

    // epilogue: bias + ELU + store, accumulating per-thread column stats
    float colsum[TC], colsq[TC];
    #pragma unroll
    for (int j = 0; j < TC; j++) { colsum[j] = 0.f; colsq[j] = 0.f; }
    #pragma unroll
    for (int m = 0; m < 4; m++) {
        int n = row0 + ty * 4 + m;
        bool valid = (n < NN);
        #pragma unroll
        for (int p = 0; p < NP; p++) {
            float lo, hi;
            unpack2(acc[m][p], lo, hi);
            int o = tx * TC + p * 2;
            float v0 = eluf(lo + bias[o]);
            float v1 = eluf(hi + bias[o + 1]);
            if (valid) {
                out[n * COUT + o]     = v0;
                out[n * COUT + o + 1] = v1;
                colsum[p * 2]     += v0;
                colsq[p * 2]      += v0 * v0;
                colsum[p * 2 + 1] += v1;
                colsq[p * 2 + 1]  += v1 * v1;
            }
        }
    }
    // reuse As/Bs smem for 16-way column reduce (16 ty-groups per column)
    float* Rs = &As[0][0];   // >= 16*COUT floats
    float* Rq = &Bs[0];      // >= 16*COUT floats
    #pragma unroll
    for (int j = 0; j < TC; j++) {
        int o = tx * TC + j;
        Rs[o * 16 + ty] = colsum[j];
        Rq[o * 16 + ty] = colsq[j];
    }
    __syncthreads();
    if (tid < COUT) {
        float s = 0.f, q = 0.f;
        #pragma unroll
        for (int r = 0; r < 16; r++) { s += Rs[tid * 16 + r]; q += Rq[tid * 16 + r]; }
        atomicAdd(&bnsum[tid], s);
        atomicAdd(&bnsq[tid], q);
    }
}

// ---------------- BN finalize + apply + ELU (fused) ----------------
template <int C>
__global__ void k_bnapply(const float* __restrict__ t, float* __restrict__ h,
                          const float* __restrict__ gamma, const float* __restrict__ beta,
                          const float* __restrict__ bsum, const float* __restrict__ bsq) {
    __shared__ float sscale[C], sshift[C];
    int tid = threadIdx.x;
    if (tid < C) {
        float m = bsum[tid] * (1.f / NN);
        float var = bsq[tid] * (1.f / NN) - m * m;
        float sc = rsqrtf(var + 1e-5f) * gamma[tid];
        sscale[tid] = sc;
        sshift[tid] = beta[tid] - m * sc;
    }
    __syncthreads();
    int idx = blockIdx.x * blockDim.x + tid;
    if (idx < NN * C) {
        int c = idx % C;
        h[idx] = eluf(t[idx] * sscale[c] + sshift[c]);
    }
}

// ---------------- FC head + global sum, fused BN2 finalize+apply ----------------
__global__ void __launch_bounds__(256) k_fc(const float* __restrict__ t2,
                                            const float* __restrict__ w1,
                                            const float* __restrict__ b1,
                                            const float* __restrict__ w2,
                                            const float* __restrict__ b2,
                                            const float* __restrict__ gamma,
                                            const float* __restrict__ beta,
                                            const float* __restrict__ bsum,
                                            const float* __restrict__ bsq,
                                            float* __restrict__ out) {
    __shared__ float sw[64 * 128];
    int tid = threadIdx.x;
    int lane = tid & 31, warp = tid >> 5;
    #pragma unroll
    for (int l = tid; l < 64 * 128 / 4; l += 256)
        ((float4*)sw)[l] = ((const float4*)w1)[l];
    float b1v[4], w2v[4];
    #pragma unroll
    for (int j = 0; j < 4; j++) {
        b1v[j] = b1[j * 32 + lane];
        w2v[j] = w2[j * 32 + lane];
    }
    float b2v = b2[0];
    float scl0, sft0, scl1, sft1;
    {
        float m = bsum[lane] * (1.f / NN);
        float var = bsq[lane] * (1.f / NN) - m * m;
        scl0 = rsqrtf(var + 1e-5f) * gamma[lane];
        sft0 = beta[lane] - m * scl0;
        int c = lane + 32;
        m = bsum[c] * (1.f / NN);
        var = bsq[c] * (1.f / NN) - m * m;
        scl1 = rsqrtf(var + 1e-5f) * gamma[c];
        sft1 = beta[c] - m * scl1;
    }
    __syncthreads();

    float local = 0.f;
    for (int n = blockIdx.x * 8 + warp; n < NN; n += gridDim.x * 8) {
        float hv0 = eluf(t2[n * 64 + lane] * scl0 + sft0);
        float hv1 = eluf(t2[n * 64 + 32 + lane] * scl1 + sft1);
        float s0 = b1v[0], s1 = b1v[1], s2 = b1v[2], s3 = b1v[3];
        #pragma unroll
        for (int i = 0; i < 64; i++) {
            float hv = __shfl_sync(0xffffffffu, (i < 32) ? hv0 : hv1, i & 31);
            s0 += hv * sw[i * 128 + lane];
            s1 += hv * sw[i * 128 + 32 + lane];
            s2 += hv * sw[i * 128 + 64 + lane];
            s3 += hv * sw[i * 128 + 96 + lane];
        }
        float contrib = eluf(s0) * w2v[0] + eluf(s1) * w2v[1]
                      + eluf(s2) * w2v[2] + eluf(s3) * w2v[3];
        #pragma unroll
        for (int off = 16; off > 0; off >>= 1)
            contrib += __shfl_xor_sync(0xffffffffu, contrib, off);
        if (lane == 0) local += eluf(contrib + b2v);
    }
    if (lane == 0) atomicAdd(out, local);
}

// ---------------- launch ----------------
extern "C" void kernel_launch(void* const* d_in, const int* in_sizes, int n_in,
                              void* d_out, int out_size) {
    const float* x        = (const float*)d_in[0];
    const int*   ei       = (const int*)d_in[1];
    const float* ea       = (const float*)d_in[2];
    const float* nn1_w1   = (const float*)d_in[3];
    const float* nn1_b1   = (const float*)d_in[4];
    const float* nn1_w2   = (const float*)d_in[5];
    const float* nn1_b2   = (const float*)d_in[6];
    const float* c1_root  = (const float*)d_in[7];
    const float* c1_bias  = (const float*)d_in[8];
    const float* bn1_g    = (const float*)d_in[9];
    const float* bn1_b    = (const float*)d_in[10];
    const float* nn2_w1   = (const float*)d_in[11];
    const float* nn2_b1   = (const float*)d_in[12];
    const float* nn2_w2   = (const float*)d_in[13];
    const float* nn2_b2   = (const float*)d_in[14];
    const float* c2_root  = (const float*)d_in[15];
    const float* c2_bias  = (const float*)d_in[16];
    const float* bn2_g    = (const float*)d_in[17];
    const float* bn2_b    = (const float*)d_in[18];
    const float* fc1_w    = (const float*)d_in[19];
    const float* fc1_b    = (const float*)d_in[20];
    const float* fc2_w    = (const float*)d_in[21];
    const float* fc2_b    = (const float*)d_in[22];
    float* out = (float*)d_out;

    float *pA1, *pA2, *pW1, *pW2, *ph1e, *ph2e, *pt1, *ph1, *pt2, *pbn;
    cudaGetSymbolAddress((void**)&pA1, g_A1);
    cudaGetSymbolAddress((void**)&pA2, g_A2);
    cudaGetSymbolAddress((void**)&pW1, g_W1);
    cudaGetSymbolAddress((void**)&pW2, g_W2);
    cudaGetSymbolAddress((void**)&ph1e, g_h1e);
    cudaGetSymbolAddress((void**)&ph2e, g_h2e);
    cudaGetSymbolAddress((void**)&pt1, g_t1);
    cudaGetSymbolAddress((void**)&ph1, g_h1);
    cudaGetSymbolAddress((void**)&pt2, g_t2);
    cudaGetSymbolAddress((void**)&pbn, g_bn);

    k_init<<<40, 256>>>(out);
    k_edgemlp<<<313, 256>>>(ea, ei, nn1_w1, nn1_b1, nn2_w1, nn2_b1);
    k_scan<<<1, 1024>>>();
    k_fill<<<313, 256>>>(ei);
    k_prepW<<<270, 256>>>(nn1_w2, nn1_b2, c1_root, nn2_w2, nn2_b2, c2_root);

    // conv1: warp-per-node gather -> gemm (+bn1 stats fused) -> bnapply (finalize fused)
    k_gather16<<<1250, 256>>>(ei, x, ph1e, pA1);
    k_gemm<432, 32, 16><<<(NN + 63) / 64, 256>>>(pA1, pW1, c1_bias, pt1, pbn + 0, pbn + 64);
    k_bnapply<32><<<(NN * 32 + 255) / 256, 256>>>(pt1, ph1, bn1_g, bn1_b, pbn + 0, pbn + 64);

    // conv2: warp-per-node gather -> gemm (+bn2 stats fused)
    k_gather32<<<1250, 256>>>(ei, ph1, ph2e, pA2);
    k_gemm<864, 64, 32><<<(NN + 63) / 64, 256>>>(pA2, pW2, c2_bias, pt2, pbn + 128, pbn + 192);

    // head: BN2 finalize+apply fused into fc
    k_fc<<<148, 256>>>(pt2, fc1_w, fc1_b, fc2_w, fc2_b,
                       bn2_g, bn2_b, pbn + 128, pbn + 192, out);
}

// round 14
// speedup vs baseline: 1.6935x; 1.0002x over previous
#include <cuda_runtime.h>
#include <cuda_bf16.h>

#define NN 10000
#define NE 80000

// ---------------- scratch (static device memory, no allocs; zero-init at load) -------
// Self-cleaning invariants (maintained across graph replays):
//   g_deg  : zero at entry; edgemlp atomics fill; k_scan zeroes after final read.
//   g_bn[0:128]   (bn1): zero before gemm1; gemm1 accumulates; bnapply reads;
//                        k_gather32 block0 zeroes (stream-after bnapply).
//   g_bn[128:256] (bn2): zero before gemm2; k_bnapply block0 zeroes it (stream-before
//                        gemm2); gemm2 accumulates; k_fc reads.
//   out[0]: k_bnapply block0 zeroes (stream-before k_fc's atomicAdd).
__device__ int   g_deg[NN];
__device__ int   g_offs[NN + 1];
__device__ int   g_cursor[NN];
__device__ int   g_csr[NE];
__device__ float g_h1e[NE * 25];      // relu(ea@nn1_w1+b1)
__device__ float g_h2e[NE * 25];      // relu(ea@nn2_w1+b2_1)
__device__ float g_A1[NN * 432];      // [S1/deg | Xsum1/deg | x]
__device__ float g_A2[NN * 864];      // [S2/deg | Hsum/deg | h1]
__device__ float g_W1[432 * 32];      // [w2_re ; b2_re ; root]
__device__ float g_W2[864 * 64];
__device__ float g_t1[NN * 32];       // elu(conv1) pre-BN
__device__ float g_h1[NN * 32];       // elu(bn1(t1))
__device__ float g_t2[NN * 64];       // elu(conv2) pre-BN
__device__ float g_bn[256];           // sum1[0:32] sq1[64:96] sum2[128:192] sq2[192:256]

__device__ __forceinline__ float eluf(float x) { return x > 0.f ? x : expm1f(x); }

// ---- packed f32x2 helpers (Blackwell FFMA2: 2x fp32 throughput) ----
typedef unsigned long long ull;
__device__ __forceinline__ ull pack2(float lo, float hi) {
    ull d; asm("mov.b64 %0, {%1, %2};" : "=l"(d) : "f"(lo), "f"(hi)); return d;
}
__device__ __forceinline__ void unpack2(ull v, float& lo, float& hi) {
    asm("mov.b64 {%0, %1}, %2;" : "=f"(lo), "=f"(hi) : "l"(v));
}
__device__ __forceinline__ ull ffma2(ull a, ull b, ull c) {
    ull d; asm("fma.rn.f32x2 %0, %1, %2, %3;" : "=l"(d) : "l"(a), "l"(b), "l"(c)); return d;
}

// ---------------- build augmented weight matrix element ----------------
template <int CIN, int COUT>
__device__ __forceinline__ void prepW_elem(int idx, const float* __restrict__ w2,
                                           const float* __restrict__ b2,
                                           const float* __restrict__ root,
                                           float* __restrict__ W) {
    constexpr int KA = 25 * CIN + 2 * CIN;
    if (idx >= KA * COUT) return;
    int kidx = idx / COUT, o = idx % COUT;
    float v;
    if (kidx < 25 * CIN) {
        int k = kidx / CIN, i = kidx % CIN;
        v = w2[(k * CIN + i) * COUT + o];
    } else if (kidx < 25 * CIN + CIN) {
        int i = kidx - 25 * CIN;
        v = b2[i * COUT + o];
    } else {
        int i = kidx - 25 * CIN - CIN;
        v = root[i * COUT + o];
    }
    W[idx] = v;
}

// ------- fused: edge MLP (both convs) + degree histogram + both prepW (grid split) ----
__global__ void __launch_bounds__(256) k_edgemlp(
        const float* __restrict__ ea, const int* __restrict__ ei,
        const float* __restrict__ w1a, const float* __restrict__ b1a,
        const float* __restrict__ w1b, const float* __restrict__ b1b,
        const float* __restrict__ w2a, const float* __restrict__ b2a, const float* __restrict__ roota,
        const float* __restrict__ w2b, const float* __restrict__ b2b, const float* __restrict__ rootb) {
    int bid = blockIdx.x, tid = threadIdx.x;
    if (bid >= 313) {
        int idx = bid - 313;
        if (idx < 54) prepW_elem<16, 32>(idx * 256 + tid, w2a, b2a, roota, g_W1);
        else          prepW_elem<32, 64>((idx - 54) * 256 + tid, w2b, b2b, rootb, g_W2);
        return;
    }
    __shared__ float sA[225];
    __shared__ float sB[225];
    for (int l = tid; l < 225; l += 256) {
        sA[l] = (l < 200) ? w1a[l] : b1a[l - 200];
        sB[l] = (l < 200) ? w1b[l] : b1b[l - 200];
    }
    __syncthreads();
    int e = bid * 256 + tid;
    if (e >= NE) return;
    atomicAdd(&g_deg[ei[NE + e]], 1);
    float4 a0 = *(const float4*)&ea[e * 8];
    float4 a1 = *(const float4*)&ea[e * 8 + 4];
    float a[8] = {a0.x, a0.y, a0.z, a0.w, a1.x, a1.y, a1.z, a1.w};
    #pragma unroll
    for (int k = 0; k < 25; k++) {
        float s = sA[200 + k];
        #pragma unroll
        for (int i = 0; i < 8; i++) s += a[i] * sA[i * 25 + k];
        g_h1e[e * 25 + k] = fmaxf(s, 0.f);
    }
    #pragma unroll
    for (int k = 0; k < 25; k++) {
        float s = sB[200 + k];
        #pragma unroll
        for (int i = 0; i < 8; i++) s += a[i] * sB[i * 25 + k];
        g_h2e[e * 25 + k] = fmaxf(s, 0.f);
    }
}

// ---------------- exclusive scan over 10000 degrees (single block) + deg self-clean --
__global__ void k_scan() {
    __shared__ int part[1024];
    int t = threadIdx.x;
    int base = t * 10;
    int s = 0;
    if (base < NN) {
        #pragma unroll
        for (int j = 0; j < 10; j++) if (base + j < NN) s += g_deg[base + j];
    }
    part[t] = s;
    __syncthreads();
    for (int off = 1; off < 1024; off <<= 1) {
        int v = 0;
        if (t >= off) v = part[t - off];
        __syncthreads();
        part[t] += v;
        __syncthreads();
    }
    int excl = (t == 0) ? 0 : part[t - 1];
    if (base < NN) {
        int run = excl;
        #pragma unroll
        for (int j = 0; j < 10; j++) {
            if (base + j < NN) {
                g_offs[base + j] = run;
                g_cursor[base + j] = run;
                run += g_deg[base + j];
            }
        }
        // self-clean for next call (edgemlp atomics need zeros)
        #pragma unroll
        for (int j = 0; j < 10; j++) if (base + j < NN) g_deg[base + j] = 0;
    }
    if (t == 1023) g_offs[NN] = part[1023];
}

// ---------------- CSR fill ----------------
__global__ void k_fill(const int* __restrict__ ei) {
    int e = blockIdx.x * blockDim.x + threadIdx.x;
    if (e < NE) {
        int d = ei[NE + e];
        int pos = atomicAdd(&g_cursor[d], 1);
        g_csr[pos] = e;
    }
}

// ------- warp-per-node gather of rank-1 outer products (no barriers, no smem) -------
// CIN=32: lane = column i; acc[k] (k=0..24) accumulates h[k]*x[i] via shfl broadcast.
// Block 0 also zeroes bn1 stats (consumed by the immediately preceding bnapply).
__global__ void __launch_bounds__(256) k_gather32(const int* __restrict__ ei,
                                                  const float* __restrict__ xfeat,
                                                  const float* __restrict__ hE,
                                                  float* __restrict__ A) {
    int lane = threadIdx.x & 31, warp = threadIdx.x >> 5;
    if (blockIdx.x == 0 && threadIdx.x < 128) g_bn[threadIdx.x] = 0.f;
    constexpr int KA = 864;
    for (int n = blockIdx.x * 8 + warp; n < NN; n += gridDim.x * 8) {
        int e0 = g_offs[n], e1 = g_offs[n + 1];
        float acc[25];
        #pragma unroll
        for (int k = 0; k < 25; k++) acc[k] = 0.f;
        float xs = 0.f;
        for (int p = e0; p < e1; p++) {
            int e = __ldg(&g_csr[p]);
            int src = __ldg(&ei[e]);
            float h = (lane < 25) ? hE[e * 25 + lane] : 0.f;
            float xv = xfeat[src * 32 + lane];
            #pragma unroll
            for (int k = 0; k < 25; k++)
                acc[k] += __shfl_sync(0xffffffffu, h, k) * xv;
            xs += xv;
        }
        float inv = 1.f / fmaxf((float)(e1 - e0), 1.f);
        float* An = &A[n * KA];
        #pragma unroll
        for (int k = 0; k < 25; k++) An[k * 32 + lane] = acc[k] * inv;
        An[800 + lane] = xs * inv;
        An[832 + lane] = xfeat[n * 32 + lane];
    }
}

// CIN=16: half-warps split k-range (lanes 0-15: k=0..12, lanes 16-31: k=13..24).
__global__ void __launch_bounds__(256) k_gather16(const int* __restrict__ ei,
                                                  const float* __restrict__ xfeat,
                                                  const float* __restrict__ hE,
                                                  float* __restrict__ A) {
    constexpr int KA = 432;
    int lane = threadIdx.x & 31, warp = threadIdx.x >> 5;
    int col = lane & 15;
    int kbase = (lane >> 4) * 13;   // 0 or 13
    for (int n = blockIdx.x * 8 + warp; n < NN; n += gridDim.x * 8) {
        int e0 = g_offs[n], e1 = g_offs[n + 1];
        float acc[13];
        #pragma unroll
        for (int j = 0; j < 13; j++) acc[j] = 0.f;
        float xs = 0.f;
        for (int p = e0; p < e1; p++) {
            int e = __ldg(&g_csr[p]);
            int src = __ldg(&ei[e]);
            float h = (lane < 25) ? hE[e * 25 + lane] : 0.f;
            float xv = xfeat[src * 16 + col];
            #pragma unroll
            for (int j = 0; j < 13; j++) {
                int k = kbase + j;
                float hk = __shfl_sync(0xffffffffu, h, k < 25 ? k : 0);
                if (k < 25) acc[j] += hk * xv;
            }
            xs += xv;
        }
        float inv = 1.f / fmaxf((float)(e1 - e0), 1.f);
        float* An = &A[n * KA];
        #pragma unroll
        for (int j = 0; j < 13; j++) {
            int k = kbase + j;
            if (k < 25) An[k * 16 + col] = acc[j] * inv;
        }
        if (lane < 16) {
            An[400 + lane] = xs * inv;
            An[416 + lane] = xfeat[n * 16 + lane];
        }
    }
}

// ------- dense GEMM  out = elu(A[NN,KA] @ W[KA,COUT] + bias), packed f32x2 FMA -------
// BM=96 -> 105 tiles <= 148 SMs: single wave, no serial tail. 256 thr, 6 rows x TC cols
// per thread. Fused BN-stat epilogue (smem 16-way reduce + one atomic per column).
template <int KA, int COUT, int BK>
__global__ void __launch_bounds__(256) k_gemm(const float* __restrict__ A,
                                              const float* __restrict__ W,
                                              const float* __restrict__ bias,
                                              float* __restrict__ out,
                                              float* __restrict__ bnsum,
                                              float* __restrict__ bnsq) {
    constexpr int BM = 96;
    constexpr int RM = 6;           // rows per thread
    constexpr int TC = COUT / 16;   // cols per thread (2 or 4)
    constexpr int NP = TC / 2;      // f32x2 pairs (1 or 2)
    __shared__ float As[BK][BM];
    __shared__ float Bs[BK * COUT];
    int tid = threadIdx.x;
    int tx = tid & 15, ty = tid >> 4;
    int row0 = blockIdx.x * BM;

    ull acc[RM][NP];
    #pragma unroll
    for (int m = 0; m < RM; m++)
        #pragma unroll
        for (int p = 0; p < NP; p++) acc[m][p] = 0ull;

    for (int k0 = 0; k0 < KA; k0 += BK) {
        constexpr int AF4 = BM * BK / 4;
        #pragma unroll
        for (int l = tid; l < AF4; l += 256) {
            int r = l / (BK / 4), q = l % (BK / 4);
            int gr = row0 + r;
            float4 v = make_float4(0.f, 0.f, 0.f, 0.f);
            if (gr < NN) v = *(const float4*)&A[gr * KA + k0 + q * 4];
            As[q * 4 + 0][r] = v.x;
            As[q * 4 + 1][r] = v.y;
            As[q * 4 + 2][r] = v.z;
            As[q * 4 + 3][r] = v.w;
        }
        constexpr int BF4 = BK * COUT / 4;
        const float4* Wp = (const float4*)&W[k0 * COUT];
        #pragma unroll
        for (int l = tid; l < BF4; l += 256) ((float4*)Bs)[l] = Wp[l];
        __syncthreads();

        #pragma unroll
        for (int kk = 0; kk < BK; kk++) {
            ull bp[NP];
            if (NP == 2) {
                float4 bq = *(const float4*)&Bs[kk * COUT + tx * 4];
                bp[0] = pack2(bq.x, bq.y);
                bp[1] = pack2(bq.z, bq.w);
            } else {
                float2 bq = *(const float2*)&Bs[kk * COUT + tx * 2];
                bp[0] = pack2(bq.x, bq.y);
            }
            // 6 rows via 3x LDS.64 (8B aligned: ty*6 is even)
            float2 a01 = *(const float2*)&As[kk][ty * RM];
            float2 a23 = *(const float2*)&As[kk][ty * RM + 2];
            float2 a45 = *(const float2*)&As[kk][ty * RM + 4];
            ull aa[RM];
            aa[0] = pack2(a01.x, a01.x);
            aa[1] = pack2(a01.y, a01.y);
            aa[2] = pack2(a23.x, a23.x);
            aa[3] = pack2(a23.y, a23.y);
            aa[4] = pack2(a45.x, a45.x);
            aa[5] = pack2(a45.y, a45.y);
            #pragma unroll
            for (int m = 0; m < RM; m++)
                #pragma unroll
                for (int p = 0; p < NP; p++)
                    acc[m][p] = ffma2(aa[m], bp[p], acc[m][p]);
        }
        __syncthreads();
    }

    // epilogue: bias + ELU + store, accumulating per-thread column stats
    float colsum[TC], colsq[TC];
    #pragma unroll
    for (int j = 0; j < TC; j++) { colsum[j] = 0.f; colsq[j] = 0.f; }
    #pragma unroll
    for (int m = 0; m < RM; m++) {
        int n = row0 + ty * RM + m;
        bool valid = (n < NN);
        #pragma unroll
        for (int p = 0; p < NP; p++) {
            float lo, hi;
            unpack2(acc[m][p], lo, hi);
            int o = tx * TC + p * 2;
            float v0 = eluf(lo + bias[o]);
            float v1 = eluf(hi + bias[o + 1]);
            if (valid) {
                *(float2*)&out[n * COUT + o] = make_float2(v0, v1);
                colsum[p * 2]     += v0;
                colsq[p * 2]      += v0 * v0;
                colsum[p * 2 + 1] += v1;
                colsq[p * 2 + 1]  += v1 * v1;
            }
        }
    }
    // reuse As/Bs smem for 16-way column reduce (16 ty-groups per column)
    float* Rs = &As[0][0];   // >= 16*COUT floats
    float* Rq = &Bs[0];      // >= 16*COUT floats
    #pragma unroll
    for (int j = 0; j < TC; j++) {
        int o = tx * TC + j;
        Rs[o * 16 + ty] = colsum[j];
        Rq[o * 16 + ty] = colsq[j];
    }
    __syncthreads();
    if (tid < COUT) {
        float s = 0.f, q = 0.f;
        #pragma unroll
        for (int r = 0; r < 16; r++) { s += Rs[tid * 16 + r]; q += Rq[tid * 16 + r]; }
        atomicAdd(&bnsum[tid], s);
        atomicAdd(&bnsq[tid], q);
    }
}

// ---------------- BN finalize + apply + ELU (fused); block0 zeroes bn2 + out ---------
template <int C>
__global__ void k_bnapply(const float* __restrict__ t, float* __restrict__ h,
                          const float* __restrict__ gamma, const float* __restrict__ beta,
                          const float* __restrict__ bsum, const float* __restrict__ bsq,
                          float* __restrict__ out) {
    __shared__ float sscale[C], sshift[C];
    int tid = threadIdx.x;
    if (blockIdx.x == 0) {
        if (tid < 128) g_bn[128 + tid] = 0.f;   // bn2 slots (before gemm2 accumulates)
        if (tid == 128) out[0] = 0.f;           // before k_fc atomicAdd
    }
    if (tid < C) {
        float m = bsum[tid] * (1.f / NN);
        float var = bsq[tid] * (1.f / NN) - m * m;
        float sc = rsqrtf(var + 1e-5f) * gamma[tid];
        sscale[tid] = sc;
        sshift[tid] = beta[tid] - m * sc;
    }
    __syncthreads();
    int idx = blockIdx.x * blockDim.x + tid;
    if (idx < NN * C) {
        int c = idx % C;
        h[idx] = eluf(t[idx] * sscale[c] + sshift[c]);
    }
}

// ---------------- FC head + global sum, fused BN2 finalize+apply ----------------
__global__ void __launch_bounds__(256) k_fc(const float* __restrict__ t2,
                                            const float* __restrict__ w1,
                                            const float* __restrict__ b1,
                                            const float* __restrict__ w2,
                                            const float* __restrict__ b2,
                                            const float* __restrict__ gamma,
                                            const float* __restrict__ beta,
                                            const float* __restrict__ bsum,
                                            const float* __restrict__ bsq,
                                            float* __restrict__ out) {
    __shared__ float sw[64 * 128];
    int tid = threadIdx.x;
    int lane = tid & 31, warp = tid >> 5;
    #pragma unroll
    for (int l = tid; l < 64 * 128 / 4; l += 256)
        ((float4*)sw)[l] = ((const float4*)w1)[l];
    float b1v[4], w2v[4];
    #pragma unroll
    for (int j = 0; j < 4; j++) {
        b1v[j] = b1[j * 32 + lane];
        w2v[j] = w2[j * 32 + lane];
    }
    float b2v = b2[0];
    float scl0, sft0, scl1, sft1;
    {
        float m = bsum[lane] * (1.f / NN);
        float var = bsq[lane] * (1.f / NN) - m * m;
        scl0 = rsqrtf(var + 1e-5f) * gamma[lane];
        sft0 = beta[lane] - m * scl0;
        int c = lane + 32;
        m = bsum[c] * (1.f / NN);
        var = bsq[c] * (1.f / NN) - m * m;
        scl1 = rsqrtf(var + 1e-5f) * gamma[c];
        sft1 = beta[c] - m * scl1;
    }
    __syncthreads();

    float local = 0.f;
    for (int n = blockIdx.x * 8 + warp; n < NN; n += gridDim.x * 8) {
        float hv0 = eluf(t2[n * 64 + lane] * scl0 + sft0);
        float hv1 = eluf(t2[n * 64 + 32 + lane] * scl1 + sft1);
        float s0 = b1v[0], s1 = b1v[1], s2 = b1v[2], s3 = b1v[3];
        #pragma unroll
        for (int i = 0; i < 64; i++) {
            float hv = __shfl_sync(0xffffffffu, (i < 32) ? hv0 : hv1, i & 31);
            s0 += hv * sw[i * 128 + lane];
            s1 += hv * sw[i * 128 + 32 + lane];
            s2 += hv * sw[i * 128 + 64 + lane];
            s3 += hv * sw[i * 128 + 96 + lane];
        }
        float contrib = eluf(s0) * w2v[0] + eluf(s1) * w2v[1]
                      + eluf(s2) * w2v[2] + eluf(s3) * w2v[3];
        #pragma unroll
        for (int off = 16; off > 0; off >>= 1)
            contrib += __shfl_xor_sync(0xffffffffu, contrib, off);
        if (lane == 0) local += eluf(contrib + b2v);
    }
    if (lane == 0) atomicAdd(out, local);
}

// ---------------- launch ----------------
extern "C" void kernel_launch(void* const* d_in, const int* in_sizes, int n_in,
                              void* d_out, int out_size) {
    const float* x        = (const float*)d_in[0];
    const int*   ei       = (const int*)d_in[1];
    const float* ea       = (const float*)d_in[2];
    const float* nn1_w1   = (const float*)d_in[3];
    const float* nn1_b1   = (const float*)d_in[4];
    const float* nn1_w2   = (const float*)d_in[5];
    const float* nn1_b2   = (const float*)d_in[6];
    const float* c1_root  = (const float*)d_in[7];
    const float* c1_bias  = (const float*)d_in[8];
    const float* bn1_g    = (const float*)d_in[9];
    const float* bn1_b    = (const float*)d_in[10];
    const float* nn2_w1   = (const float*)d_in[11];
    const float* nn2_b1   = (const float*)d_in[12];
    const float* nn2_w2   = (const float*)d_in[13];
    const float* nn2_b2   = (const float*)d_in[14];
    const float* c2_root  = (const float*)d_in[15];
    const float* c2_bias  = (const float*)d_in[16];
    const float* bn2_g    = (const float*)d_in[17];
    const float* bn2_b    = (const float*)d_in[18];
    const float* fc1_w    = (const float*)d_in[19];
    const float* fc1_b    = (const float*)d_in[20];
    const float* fc2_w    = (const float*)d_in[21];
    const float* fc2_b    = (const float*)d_in[22];
    float* out = (float*)d_out;

    float *pA1, *pA2, *pW1, *pW2, *ph1e, *ph2e, *pt1, *ph1, *pt2, *pbn;
    cudaGetSymbolAddress((void**)&pA1, g_A1);
    cudaGetSymbolAddress((void**)&pA2, g_A2);
    cudaGetSymbolAddress((void**)&pW1, g_W1);
    cudaGetSymbolAddress((void**)&pW2, g_W2);
    cudaGetSymbolAddress((void**)&ph1e, g_h1e);
    cudaGetSymbolAddress((void**)&ph2e, g_h2e);
    cudaGetSymbolAddress((void**)&pt1, g_t1);
    cudaGetSymbolAddress((void**)&ph1, g_h1);
    cudaGetSymbolAddress((void**)&pt2, g_t2);
    cudaGetSymbolAddress((void**)&pbn, g_bn);

    // front end: edge MLP + deg atomics + both prepW (grid split), scan, CSR fill
    k_edgemlp<<<583, 256>>>(ea, ei, nn1_w1, nn1_b1, nn2_w1, nn2_b1,
                            nn1_w2, nn1_b2, c1_root, nn2_w2, nn2_b2, c2_root);
    k_scan<<<1, 1024>>>();
    k_fill<<<313, 256>>>(ei);

    // conv1: warp-per-node gather -> gemm (+bn1 stats) -> bnapply (+zero bn2/out)
    k_gather16<<<1250, 256>>>(ei, x, ph1e, pA1);
    k_gemm<432, 32, 16><<<(NN + 95) / 96, 256>>>(pA1, pW1, c1_bias, pt1, pbn + 0, pbn + 64);
    k_bnapply<32><<<(NN * 32 + 255) / 256, 256>>>(pt1, ph1, bn1_g, bn1_b, pbn + 0, pbn + 64, out);

    // conv2: warp-per-node gather (+zero bn1) -> gemm (+bn2 stats)
    k_gather32<<<1250, 256>>>(ei, ph1, ph2e, pA2);
    k_gemm<864, 64, 32><<<(NN + 95) / 96, 256>>>(pA2, pW2, c2_bias, pt2, pbn + 128, pbn + 192);

    // head: BN2 finalize+apply fused into fc
    k_fc<<<148, 256>>>(pt2, fc1_w, fc1_b, fc2_w, fc2_b,
                       bn2_g, bn2_b, pbn + 128, pbn + 192, out);
}

// round 15
// speedup vs baseline: 1.7785x; 1.0502x over previous
#include <cuda_runtime.h>
#include <cuda_bf16.h>

#define NN 10000
#define NE 80000

// ---------------- scratch (static device memory, no allocs; zero-init at load) -------
// Self-cleaning invariants (maintained across graph replays):
//   g_deg  : zero at entry; edgemlp atomics fill; k_scan zeroes after final read.
//   g_bn[0:128]   (bn1): gemm1 accumulates; bnapply reads; k_gather32 block0 zeroes.
//   g_bn[128:256] (bn2): k_bnapply block0 zeroes (stream-before gemm2); k_fc reads.
//   out[0]: k_bnapply block0 zeroes (stream-before k_fc's atomicAdd).
__device__ int   g_deg[NN];
__device__ int   g_offs[NN + 1];
__device__ int   g_cursor[NN];
__device__ int2  g_csr[NE];           // (edge id, src node) packed
__device__ float g_h1e[NE * 25];      // relu(ea@nn1_w1+b1)
__device__ float g_h2e[NE * 25];      // relu(ea@nn2_w1+b2_1)
__device__ float g_A1[NN * 432];      // [S1/deg | Xsum1/deg | x]
__device__ float g_A2[NN * 864];      // [S2/deg | Hsum/deg | h1]
__device__ float g_W1[432 * 32];      // [w2_re ; b2_re ; root]
__device__ float g_W2[864 * 64];
__device__ float g_t1[NN * 32];       // elu(conv1) pre-BN
__device__ float g_h1[NN * 32];       // elu(bn1(t1))
__device__ float g_t2[NN * 64];       // elu(conv2) pre-BN
__device__ float g_bn[256];           // sum1[0:32] sq1[64:96] sum2[128:192] sq2[192:256]

__device__ __forceinline__ float eluf(float x) { return x > 0.f ? x : expm1f(x); }

// ---- packed f32x2 helpers (Blackwell FFMA2: 2x fp32 throughput) ----
typedef unsigned long long ull;
__device__ __forceinline__ ull pack2(float lo, float hi) {
    ull d; asm("mov.b64 %0, {%1, %2};" : "=l"(d) : "f"(lo), "f"(hi)); return d;
}
__device__ __forceinline__ void unpack2(ull v, float& lo, float& hi) {
    asm("mov.b64 {%0, %1}, %2;" : "=f"(lo), "=f"(hi) : "l"(v));
}
__device__ __forceinline__ ull ffma2(ull a, ull b, ull c) {
    ull d; asm("fma.rn.f32x2 %0, %1, %2, %3;" : "=l"(d) : "l"(a), "l"(b), "l"(c)); return d;
}

// ---------------- build augmented weight matrix element ----------------
template <int CIN, int COUT>
__device__ __forceinline__ void prepW_elem(int idx, const float* __restrict__ w2,
                                           const float* __restrict__ b2,
                                           const float* __restrict__ root,
                                           float* __restrict__ W) {
    constexpr int KA = 25 * CIN + 2 * CIN;
    if (idx >= KA * COUT) return;
    int kidx = idx / COUT, o = idx % COUT;
    float v;
    if (kidx < 25 * CIN) {
        int k = kidx / CIN, i = kidx % CIN;
        v = w2[(k * CIN + i) * COUT + o];
    } else if (kidx < 25 * CIN + CIN) {
        int i = kidx - 25 * CIN;
        v = b2[i * COUT + o];
    } else {
        int i = kidx - 25 * CIN - CIN;
        v = root[i * COUT + o];
    }
    W[idx] = v;
}

// ------- fused: edge MLP (both convs) + degree histogram + both prepW (grid split) ----
__global__ void __launch_bounds__(256) k_edgemlp(
        const float* __restrict__ ea, const int* __restrict__ ei,
        const float* __restrict__ w1a, const float* __restrict__ b1a,
        const float* __restrict__ w1b, const float* __restrict__ b1b,
        const float* __restrict__ w2a, const float* __restrict__ b2a, const float* __restrict__ roota,
        const float* __restrict__ w2b, const float* __restrict__ b2b, const float* __restrict__ rootb) {
    int bid = blockIdx.x, tid = threadIdx.x;
    if (bid >= 313) {
        int idx = bid - 313;
        if (idx < 54) prepW_elem<16, 32>(idx * 256 + tid, w2a, b2a, roota, g_W1);
        else          prepW_elem<32, 64>((idx - 54) * 256 + tid, w2b, b2b, rootb, g_W2);
        return;
    }
    __shared__ float sA[225];
    __shared__ float sB[225];
    for (int l = tid; l < 225; l += 256) {
        sA[l] = (l < 200) ? w1a[l] : b1a[l - 200];
        sB[l] = (l < 200) ? w1b[l] : b1b[l - 200];
    }
    __syncthreads();
    int e = bid * 256 + tid;
    if (e >= NE) return;
    atomicAdd(&g_deg[ei[NE + e]], 1);
    float4 a0 = *(const float4*)&ea[e * 8];
    float4 a1 = *(const float4*)&ea[e * 8 + 4];
    float a[8] = {a0.x, a0.y, a0.z, a0.w, a1.x, a1.y, a1.z, a1.w};
    #pragma unroll
    for (int k = 0; k < 25; k++) {
        float s = sA[200 + k];
        #pragma unroll
        for (int i = 0; i < 8; i++) s += a[i] * sA[i * 25 + k];
        g_h1e[e * 25 + k] = fmaxf(s, 0.f);
    }
    #pragma unroll
    for (int k = 0; k < 25; k++) {
        float s = sB[200 + k];
        #pragma unroll
        for (int i = 0; i < 8; i++) s += a[i] * sB[i * 25 + k];
        g_h2e[e * 25 + k] = fmaxf(s, 0.f);
    }
}

// ---------------- exclusive scan over 10000 degrees (single block) + deg self-clean --
__global__ void k_scan() {
    __shared__ int part[1024];
    int t = threadIdx.x;
    int base = t * 10;
    int s = 0;
    if (base < NN) {
        #pragma unroll
        for (int j = 0; j < 10; j++) if (base + j < NN) s += g_deg[base + j];
    }
    part[t] = s;
    __syncthreads();
    for (int off = 1; off < 1024; off <<= 1) {
        int v = 0;
        if (t >= off) v = part[t - off];
        __syncthreads();
        part[t] += v;
        __syncthreads();
    }
    int excl = (t == 0) ? 0 : part[t - 1];
    if (base < NN) {
        int run = excl;
        #pragma unroll
        for (int j = 0; j < 10; j++) {
            if (base + j < NN) {
                g_offs[base + j] = run;
                g_cursor[base + j] = run;
                run += g_deg[base + j];
            }
        }
        // self-clean for next call (edgemlp atomics need zeros)
        #pragma unroll
        for (int j = 0; j < 10; j++) if (base + j < NN) g_deg[base + j] = 0;
    }
    if (t == 1023) g_offs[NN] = part[1023];
}

// ---------------- CSR fill: store (edge, src) packed — shortens gather dep chain -----
__global__ void k_fill(const int* __restrict__ ei) {
    int e = blockIdx.x * blockDim.x + threadIdx.x;
    if (e < NE) {
        int d = ei[NE + e];
        int s = ei[e];
        int pos = atomicAdd(&g_cursor[d], 1);
        g_csr[pos] = make_int2(e, s);
    }
}

// ------- warp-per-node gather of rank-1 outer products (no barriers, no smem) -------
// Software-pipelined: indices prefetched 2 edges ahead, feature data 1 edge ahead, so
// each iteration issues only independent loads and computes on last iteration's regs.
// CIN=32: lane = column i; acc[k] (k=0..24) accumulates h[k]*x[i] via shfl broadcast.
// Block 0 also zeroes bn1 stats (consumed by the immediately preceding bnapply).
__global__ void __launch_bounds__(256) k_gather32(const float* __restrict__ xfeat,
                                                  const float* __restrict__ hE,
                                                  float* __restrict__ A) {
    int lane = threadIdx.x & 31, warp = threadIdx.x >> 5;
    if (blockIdx.x == 0 && threadIdx.x < 128) g_bn[threadIdx.x] = 0.f;
    constexpr int KA = 864;
    for (int n = blockIdx.x * 8 + warp; n < NN; n += gridDim.x * 8) {
        int e0 = g_offs[n], e1 = g_offs[n + 1];
        float acc[25];
        #pragma unroll
        for (int k = 0; k < 25; k++) acc[k] = 0.f;
        float xs = 0.f;

        float hC = 0.f, xC = 0.f;
        int2 eA = make_int2(0, 0);
        if (e0 < e1) {
            int2 t0 = __ldg(&g_csr[e0]);
            hC = (lane < 25) ? hE[t0.x * 25 + lane] : 0.f;
            xC = xfeat[t0.y * 32 + lane];
            if (e0 + 1 < e1) eA = __ldg(&g_csr[e0 + 1]);
        }
        for (int p = e0; p < e1; p++) {
            int2 eB = (p + 2 < e1) ? __ldg(&g_csr[p + 2]) : eA;
            float hN = 0.f, xN = 0.f;
            if (p + 1 < e1) {
                hN = (lane < 25) ? hE[eA.x * 25 + lane] : 0.f;
                xN = xfeat[eA.y * 32 + lane];
            }
            #pragma unroll
            for (int k = 0; k < 25; k++)
                acc[k] += __shfl_sync(0xffffffffu, hC, k) * xC;
            xs += xC;
            hC = hN; xC = xN; eA = eB;
        }
        float inv = 1.f / fmaxf((float)(e1 - e0), 1.f);
        float* An = &A[n * KA];
        #pragma unroll
        for (int k = 0; k < 25; k++) An[k * 32 + lane] = acc[k] * inv;
        An[800 + lane] = xs * inv;
        An[832 + lane] = xfeat[n * 32 + lane];
    }
}

// CIN=16: half-warps split k-range (lanes 0-15: k=0..12, lanes 16-31: k=13..24).
__global__ void __launch_bounds__(256) k_gather16(const float* __restrict__ xfeat,
                                                  const float* __restrict__ hE,
                                                  float* __restrict__ A) {
    constexpr int KA = 432;
    int lane = threadIdx.x & 31, warp = threadIdx.x >> 5;
    int col = lane & 15;
    int kbase = (lane >> 4) * 13;   // 0 or 13
    for (int n = blockIdx.x * 8 + warp; n < NN; n += gridDim.x * 8) {
        int e0 = g_offs[n], e1 = g_offs[n + 1];
        float acc[13];
        #pragma unroll
        for (int j = 0; j < 13; j++) acc[j] = 0.f;
        float xs = 0.f;

        float hC = 0.f, xC = 0.f;
        int2 eA = make_int2(0, 0);
        if (e0 < e1) {
            int2 t0 = __ldg(&g_csr[e0]);
            hC = (lane < 25) ? hE[t0.x * 25 + lane] : 0.f;
            xC = xfeat[t0.y * 16 + col];
            if (e0 + 1 < e1) eA = __ldg(&g_csr[e0 + 1]);
        }
        for (int p = e0; p < e1; p++) {
            int2 eB = (p + 2 < e1) ? __ldg(&g_csr[p + 2]) : eA;
            float hN = 0.f, xN = 0.f;
            if (p + 1 < e1) {
                hN = (lane < 25) ? hE[eA.x * 25 + lane] : 0.f;
                xN = xfeat[eA.y * 16 + col];
            }
            #pragma unroll
            for (int j = 0; j < 13; j++) {
                int k = kbase + j;
                float hk = __shfl_sync(0xffffffffu, hC, k < 25 ? k : 0);
                if (k < 25) acc[j] += hk * xC;
            }
            xs += xC;
            hC = hN; xC = xN; eA = eB;
        }
        float inv = 1.f / fmaxf((float)(e1 - e0), 1.f);
        float* An = &A[n * KA];
        #pragma unroll
        for (int j = 0; j < 13; j++) {
            int k = kbase + j;
            if (k < 25) An[k * 16 + col] = acc[j] * inv;
        }
        if (lane < 16) {
            An[400 + lane] = xs * inv;
            An[416 + lane] = xfeat[n * 16 + lane];
        }
    }
}

// ------- dense GEMM  out = elu(A[NN,KA] @ W[KA,COUT] + bias), packed f32x2 FMA -------
// BM=96 -> 105 tiles <= 148 SMs: single wave. 256 thr, 6 rows x TC cols per thread.
// Fused BN-stat epilogue (smem 16-way reduce + one atomic per column).
template <int KA, int COUT, int BK>
__global__ void __launch_bounds__(256) k_gemm(const float* __restrict__ A,
                                              const float* __restrict__ W,
                                              const float* __restrict__ bias,
                                              float* __restrict__ out,
                                              float* __restrict__ bnsum,
                                              float* __restrict__ bnsq) {
    constexpr int BM = 96;
    constexpr int RM = 6;           // rows per thread
    constexpr int TC = COUT / 16;   // cols per thread (2 or 4)
    constexpr int NP = TC / 2;      // f32x2 pairs (1 or 2)
    __shared__ float As[BK][BM];
    __shared__ float Bs[BK * COUT];
    int tid = threadIdx.x;
    int tx = tid & 15, ty = tid >> 4;
    int row0 = blockIdx.x * BM;

    ull acc[RM][NP];
    #pragma unroll
    for (int m = 0; m < RM; m++)
        #pragma unroll
        for (int p = 0; p < NP; p++) acc[m][p] = 0ull;

    for (int k0 = 0; k0 < KA; k0 += BK) {
        constexpr int AF4 = BM * BK / 4;
        #pragma unroll
        for (int l = tid; l < AF4; l += 256) {
            int r = l / (BK / 4), q = l % (BK / 4);
            int gr = row0 + r;
            float4 v = make_float4(0.f, 0.f, 0.f, 0.f);
            if (gr < NN) v = *(const float4*)&A[gr * KA + k0 + q * 4];
            As[q * 4 + 0][r] = v.x;
            As[q * 4 + 1][r] = v.y;
            As[q * 4 + 2][r] = v.z;
            As[q * 4 + 3][r] = v.w;
        }
        constexpr int BF4 = BK * COUT / 4;
        const float4* Wp = (const float4*)&W[k0 * COUT];
        #pragma unroll
        for (int l = tid; l < BF4; l += 256) ((float4*)Bs)[l] = Wp[l];
        __syncthreads();

        #pragma unroll
        for (int kk = 0; kk < BK; kk++) {
            ull bp[NP];
            if (NP == 2) {
                float4 bq = *(const float4*)&Bs[kk * COUT + tx * 4];
                bp[0] = pack2(bq.x, bq.y);
                bp[1] = pack2(bq.z, bq.w);
            } else {
                float2 bq = *(const float2*)&Bs[kk * COUT + tx * 2];
                bp[0] = pack2(bq.x, bq.y);
            }
            // 6 rows via 3x LDS.64 (8B aligned: ty*6 is even)
            float2 a01 = *(const float2*)&As[kk][ty * RM];
            float2 a23 = *(const float2*)&As[kk][ty * RM + 2];
            float2 a45 = *(const float2*)&As[kk][ty * RM + 4];
            ull aa[RM];
            aa[0] = pack2(a01.x, a01.x);
            aa[1] = pack2(a01.y, a01.y);
            aa[2] = pack2(a23.x, a23.x);
            aa[3] = pack2(a23.y, a23.y);
            aa[4] = pack2(a45.x, a45.x);
            aa[5] = pack2(a45.y, a45.y);
            #pragma unroll
            for (int m = 0; m < RM; m++)
                #pragma unroll
                for (int p = 0; p < NP; p++)
                    acc[m][p] = ffma2(aa[m], bp[p], acc[m][p]);
        }
        __syncthreads();
    }

    // epilogue: bias + ELU + store, accumulating per-thread column stats
    float colsum[TC], colsq[TC];
    #pragma unroll
    for (int j = 0; j < TC; j++) { colsum[j] = 0.f; colsq[j] = 0.f; }
    #pragma unroll
    for (int m = 0; m < RM; m++) {
        int n = row0 + ty * RM + m;
        bool valid = (n < NN);
        #pragma unroll
        for (int p = 0; p < NP; p++) {
            float lo, hi;
            unpack2(acc[m][p], lo, hi);
            int o = tx * TC + p * 2;
            float v0 = eluf(lo + bias[o]);
            float v1 = eluf(hi + bias[o + 1]);
            if (valid) {
                *(float2*)&out[n * COUT + o] = make_float2(v0, v1);
                colsum[p * 2]     += v0;
                colsq[p * 2]      += v0 * v0;
                colsum[p * 2 + 1] += v1;
                colsq[p * 2 + 1]  += v1 * v1;
            }
        }
    }
    // reuse As/Bs smem for 16-way column reduce (16 ty-groups per column)
    float* Rs = &As[0][0];   // >= 16*COUT floats
    float* Rq = &Bs[0];      // >= 16*COUT floats
    #pragma unroll
    for (int j = 0; j < TC; j++) {
        int o = tx * TC + j;
        Rs[o * 16 + ty] = colsum[j];
        Rq[o * 16 + ty] = colsq[j];
    }
    __syncthreads();
    if (tid < COUT) {
        float s = 0.f, q = 0.f;
        #pragma unroll
        for (int r = 0; r < 16; r++) { s += Rs[tid * 16 + r]; q += Rq[tid * 16 + r]; }
        atomicAdd(&bnsum[tid], s);
        atomicAdd(&bnsq[tid], q);
    }
}

// ---------------- BN finalize + apply + ELU (fused); block0 zeroes bn2 + out ---------
template <int C>
__global__ void k_bnapply(const float* __restrict__ t, float* __restrict__ h,
                          const float* __restrict__ gamma, const float* __restrict__ beta,
                          const float* __restrict__ bsum, const float* __restrict__ bsq,
                          float* __restrict__ out) {
    __shared__ float sscale[C], sshift[C];
    int tid = threadIdx.x;
    if (blockIdx.x == 0) {
        if (tid < 128) g_bn[128 + tid] = 0.f;   // bn2 slots (before gemm2 accumulates)
        if (tid == 128) out[0] = 0.f;           // before k_fc atomicAdd
    }
    if (tid < C) {
        float m = bsum[tid] * (1.f / NN);
        float var = bsq[tid] * (1.f / NN) - m * m;
        float sc = rsqrtf(var + 1e-5f) * gamma[tid];
        sscale[tid] = sc;
        sshift[tid] = beta[tid] - m * sc;
    }
    __syncthreads();
    int idx = blockIdx.x * blockDim.x + tid;
    if (idx < NN * C) {
        int c = idx % C;
        h[idx] = eluf(t[idx] * sscale[c] + sshift[c]);
    }
}

// ---------------- FC head + global sum, fused BN2 finalize+apply ----------------
__global__ void __launch_bounds__(256) k_fc(const float* __restrict__ t2,
                                            const float* __restrict__ w1,
                                            const float* __restrict__ b1,
                                            const float* __restrict__ w2,
                                            const float* __restrict__ b2,
                                            const float* __restrict__ gamma,
                                            const float* __restrict__ beta,
                                            const float* __restrict__ bsum,
                                            const float* __restrict__ bsq,
                                            float* __restrict__ out) {
    __shared__ float sw[64 * 128];
    int tid = threadIdx.x;
    int lane = tid & 31, warp = tid >> 5;
    #pragma unroll
    for (int l = tid; l < 64 * 128 / 4; l += 256)
        ((float4*)sw)[l] = ((const float4*)w1)[l];
    float b1v[4], w2v[4];
    #pragma unroll
    for (int j = 0; j < 4; j++) {
        b1v[j] = b1[j * 32 + lane];
        w2v[j] = w2[j * 32 + lane];
    }
    float b2v = b2[0];
    float scl0, sft0, scl1, sft1;
    {
        float m = bsum[lane] * (1.f / NN);
        float var = bsq[lane] * (1.f / NN) - m * m;
        scl0 = rsqrtf(var + 1e-5f) * gamma[lane];
        sft0 = beta[lane] - m * scl0;
        int c = lane + 32;
        m = bsum[c] * (1.f / NN);
        var = bsq[c] * (1.f / NN) - m * m;
        scl1 = rsqrtf(var + 1e-5f) * gamma[c];
        sft1 = beta[c] - m * scl1;
    }
    __syncthreads();

    float local = 0.f;
    for (int n = blockIdx.x * 8 + warp; n < NN; n += gridDim.x * 8) {
        float hv0 = eluf(t2[n * 64 + lane] * scl0 + sft0);
        float hv1 = eluf(t2[n * 64 + 32 + lane] * scl1 + sft1);
        float s0 = b1v[0], s1 = b1v[1], s2 = b1v[2], s3 = b1v[3];
        #pragma unroll
        for (int i = 0; i < 64; i++) {
            float hv = __shfl_sync(0xffffffffu, (i < 32) ? hv0 : hv1, i & 31);
            s0 += hv * sw[i * 128 + lane];
            s1 += hv * sw[i * 128 + 32 + lane];
            s2 += hv * sw[i * 128 + 64 + lane];
            s3 += hv * sw[i * 128 + 96 + lane];
        }
        float contrib = eluf(s0) * w2v[0] + eluf(s1) * w2v[1]
                      + eluf(s2) * w2v[2] + eluf(s3) * w2v[3];
        #pragma unroll
        for (int off = 16; off > 0; off >>= 1)
            contrib += __shfl_xor_sync(0xffffffffu, contrib, off);
        if (lane == 0) local += eluf(contrib + b2v);
    }
    if (lane == 0) atomicAdd(out, local);
}

// ---------------- launch ----------------
extern "C" void kernel_launch(void* const* d_in, const int* in_sizes, int n_in,
                              void* d_out, int out_size) {
    const float* x        = (const float*)d_in[0];
    const int*   ei       = (const int*)d_in[1];
    const float* ea       = (const float*)d_in[2];
    const float* nn1_w1   = (const float*)d_in[3];
    const float* nn1_b1   = (const float*)d_in[4];
    const float* nn1_w2   = (const float*)d_in[5];
    const float* nn1_b2   = (const float*)d_in[6];
    const float* c1_root  = (const float*)d_in[7];
    const float* c1_bias  = (const float*)d_in[8];
    const float* bn1_g    = (const float*)d_in[9];
    const float* bn1_b    = (const float*)d_in[10];
    const float* nn2_w1   = (const float*)d_in[11];
    const float* nn2_b1   = (const float*)d_in[12];
    const float* nn2_w2   = (const float*)d_in[13];
    const float* nn2_b2   = (const float*)d_in[14];
    const float* c2_root  = (const float*)d_in[15];
    const float* c2_bias  = (const float*)d_in[16];
    const float* bn2_g    = (const float*)d_in[17];
    const float* bn2_b    = (const float*)d_in[18];
    const float* fc1_w    = (const float*)d_in[19];
    const float* fc1_b    = (const float*)d_in[20];
    const float* fc2_w    = (const float*)d_in[21];
    const float* fc2_b    = (const float*)d_in[22];
    float* out = (float*)d_out;

    float *pA1, *pA2, *pW1, *pW2, *ph1e, *ph2e, *pt1, *ph1, *pt2, *pbn;
    cudaGetSymbolAddress((void**)&pA1, g_A1);
    cudaGetSymbolAddress((void**)&pA2, g_A2);
    cudaGetSymbolAddress((void**)&pW1, g_W1);
    cudaGetSymbolAddress((void**)&pW2, g_W2);
    cudaGetSymbolAddress((void**)&ph1e, g_h1e);
    cudaGetSymbolAddress((void**)&ph2e, g_h2e);
    cudaGetSymbolAddress((void**)&pt1, g_t1);
    cudaGetSymbolAddress((void**)&ph1, g_h1);
    cudaGetSymbolAddress((void**)&pt2, g_t2);
    cudaGetSymbolAddress((void**)&pbn, g_bn);

    // front end: edge MLP + deg atomics + both prepW (grid split), scan, CSR fill
    k_edgemlp<<<583, 256>>>(ea, ei, nn1_w1, nn1_b1, nn2_w1, nn2_b1,
                            nn1_w2, nn1_b2, c1_root, nn2_w2, nn2_b2, c2_root);
    k_scan<<<1, 1024>>>();
    k_fill<<<313, 256>>>(ei);

    // conv1: pipelined warp-per-node gather -> gemm (+bn1 stats) -> bnapply (+zero bn2/out)
    k_gather16<<<1250, 256>>>(x, ph1e, pA1);
    k_gemm<432, 32, 16><<<(NN + 95) / 96, 256>>>(pA1, pW1, c1_bias, pt1, pbn + 0, pbn + 64);
    k_bnapply<32><<<(NN * 32 + 255) / 256, 256>>>(pt1, ph1, bn1_g, bn1_b, pbn + 0, pbn + 64, out);

    // conv2: pipelined warp-per-node gather (+zero bn1) -> gemm (+bn2 stats)
    k_gather32<<<1250, 256>>>(ph1, ph2e, pA2);
    k_gemm<864, 64, 32><<<(NN + 95) / 96, 256>>>(pA2, pW2, c2_bias, pt2, pbn + 128, pbn + 192);

    // head: BN2 finalize+apply fused into fc
    k_fc<<<148, 256>>>(pt2, fc1_w, fc1_b, fc2_w, fc2_b,
                       bn2_g, bn2_b, pbn + 128, pbn + 192, out);
}